// round 11
// baseline (speedup 1.0000x reference)
#include <cuda_runtime.h>
#include <cuda_bf16.h>
#include <math.h>
#include <stdint.h>

// ---------------- problem constants ----------------
#define B_  4
#define L_  4096
#define C_  1024
#define H_  8
#define D_  64      // C / (2H)
#define R_  512     // int(L^0.75)
#define M_  (B_*R_) // 2048 GEMM rows
#define FULL_ELEMS (B_*L_*C_)   // 16777216
#define LAMBDA_INIT 0.8f
#define EPS_ 1e-6f

// ---------------- device scratch (no allocs allowed) ----------------
__device__ float g_q   [M_*C_];
__device__ float g_k   [M_*C_];
__device__ float g_v   [M_*C_];
__device__ float g_q1  [B_*H_*R_*D_];
__device__ float g_q2  [B_*H_*R_*D_];
__device__ float g_k1  [B_*H_*R_*D_];
__device__ float g_k2  [B_*H_*R_*D_];
__device__ float g_diff[M_*C_];
__device__ float g_lam;

// bf16 hi/lo split operands for tensor-core GEMMs
__device__ __nv_bfloat16 g_xdh[M_*C_], g_xdl[M_*C_];       // downsampled x
__device__ __nv_bfloat16 g_dh [M_*C_], g_dl [M_*C_];       // head-normed diff
__device__ __nv_bfloat16 g_wh [4][C_*C_], g_wl[4][C_*C_];  // Wq,Wk,Wv,Wo

// ---------------- warp helpers ----------------
__device__ __forceinline__ float warp_sum(float v) {
    #pragma unroll
    for (int o = 16; o > 0; o >>= 1) v += __shfl_xor_sync(0xffffffffu, v, o);
    return v;
}
__device__ __forceinline__ float warp_max(float v) {
    #pragma unroll
    for (int o = 16; o > 0; o >>= 1) v = fmaxf(v, __shfl_xor_sync(0xffffffffu, v, o));
    return v;
}

// ---------------- PTX helpers (HMMA path: valid on compute_103 PTX target) ----
__device__ __forceinline__ uint32_t smem_u32(const void* p) {
    uint32_t a;
    asm("{ .reg .u64 t; cvta.to.shared.u64 t, %1; cvt.u32.u64 %0, t; }" : "=r"(a) : "l"(p));
    return a;
}
__device__ __forceinline__ void cp_async16(uint32_t dst, const void* src) {
    asm volatile("cp.async.cg.shared.global [%0], [%1], 16;" :: "r"(dst), "l"(src) : "memory");
}
__device__ __forceinline__ void ldm_x4(uint32_t* r, uint32_t addr) {
    asm volatile("ldmatrix.sync.aligned.m8n8.x4.shared.b16 {%0,%1,%2,%3}, [%4];"
                 : "=r"(r[0]), "=r"(r[1]), "=r"(r[2]), "=r"(r[3]) : "r"(addr));
}
__device__ __forceinline__ void mma_bf16(float* c, const uint32_t* a, const uint32_t* b) {
    asm volatile(
        "mma.sync.aligned.m16n8k16.row.col.f32.bf16.bf16.f32 "
        "{%0,%1,%2,%3}, {%4,%5,%6,%7}, {%8,%9}, {%0,%1,%2,%3};"
        : "+f"(c[0]), "+f"(c[1]), "+f"(c[2]), "+f"(c[3])
        : "r"(a[0]), "r"(a[1]), "r"(a[2]), "r"(a[3]), "r"(b[0]), "r"(b[1]));
}

// ---------------- fp32 -> (bf16 hi, bf16 lo) split ----------------
__device__ __forceinline__ void split4(float4 o, __nv_bfloat16* hi, __nv_bfloat16* lo, size_t base) {
    __nv_bfloat16 h0 = __float2bfloat16(o.x), h1 = __float2bfloat16(o.y);
    __nv_bfloat16 h2 = __float2bfloat16(o.z), h3 = __float2bfloat16(o.w);
    __nv_bfloat16 l0 = __float2bfloat16(o.x - __bfloat162float(h0));
    __nv_bfloat16 l1 = __float2bfloat16(o.y - __bfloat162float(h1));
    __nv_bfloat16 l2 = __float2bfloat16(o.z - __bfloat162float(h2));
    __nv_bfloat16 l3 = __float2bfloat16(o.w - __bfloat162float(h3));
    __nv_bfloat162 ha; ha.x = h0; ha.y = h1;
    __nv_bfloat162 hb; hb.x = h2; hb.y = h3;
    __nv_bfloat162 la; la.x = l0; la.y = l1;
    __nv_bfloat162 lb; lb.x = l2; lb.y = l3;
    *(__nv_bfloat162*)&hi[base]     = ha;
    *(__nv_bfloat162*)&hi[base + 2] = hb;
    *(__nv_bfloat162*)&lo[base]     = la;
    *(__nv_bfloat162*)&lo[base + 2] = lb;
}

__global__ void split_kernel(const float* __restrict__ x,
                             __nv_bfloat16* __restrict__ hi, __nv_bfloat16* __restrict__ lo) {
    int i = blockIdx.x * blockDim.x + threadIdx.x;    // n/4 threads
    float4 v = *(const float4*)&x[(size_t)i * 4];
    split4(v, hi, lo, (size_t)i * 4);
}

// ---------------- lambda scalar ----------------
__global__ void lam_kernel(const float* __restrict__ lq1, const float* __restrict__ lk1,
                           const float* __restrict__ lq2, const float* __restrict__ lk2) {
    int l = threadIdx.x;
    float s1 = lq1[l]*lk1[l] + lq1[l+32]*lk1[l+32];
    float s2 = lq2[l]*lk2[l] + lq2[l+32]*lk2[l+32];
    s1 = warp_sum(s1);
    s2 = warp_sum(s2);
    if (l == 0) g_lam = expf(s1) - expf(s2) + LAMBDA_INIT;
}

// ---------------- downsample + split: xd = 0.5*(x[8i+3] + x[8i+4]) ----------------
__global__ void downsample_kernel(const float* __restrict__ x) {
    int idx = blockIdx.x * blockDim.x + threadIdx.x;         // < 2048*256
    int c  = (idx & 255) * 4;
    int m  = idx >> 8;                                       // 0..2047
    int b  = m >> 9, i = m & 511;
    size_t src = ((size_t)b * L_ + 8 * i + 3) * C_ + c;
    float4 a  = *(const float4*)&x[src];
    float4 bb = *(const float4*)&x[src + C_];
    float4 o = { 0.5f*(a.x+bb.x), 0.5f*(a.y+bb.y), 0.5f*(a.z+bb.z), 0.5f*(a.w+bb.w) };
    split4(o, g_xdh, g_xdl, (size_t)m * C_ + c);
}

// ---------------- HMMA split-bf16 GEMM ----------------
// C[m,n] = sum_k A[m,k]*B[n,k], fp32 accum, 3 MMAs: Ah*Bh + Ah*Bl + Al*Bh.
// Block tile 128x128, 8 warps (warp tile 32x64), K-chunk 64, double-buffered cp.async.
#define BK_      64
#define TSTRIDE  144                   // bytes per SMEM row (128 data + 16 pad)
#define TSIZE    (128 * TSTRIDE)       // 18432 per tensor
#define GSTAGE   (4 * TSIZE)           // Ah, Al, Bh, Bl
#define GSM_TOTAL (2 * GSTAGE)         // 147456

template<bool SILU>
__global__ __launch_bounds__(256, 1) void gemm_tc(
    const __nv_bfloat16* __restrict__ Ah, const __nv_bfloat16* __restrict__ Al,
    const __nv_bfloat16* __restrict__ Bh, const __nv_bfloat16* __restrict__ Bl,
    float* __restrict__ Cout)
{
    extern __shared__ char smc[];
    const uint32_t sb = smem_u32(smc);
    const int t = threadIdx.x, w = t >> 5, lane = t & 31;
    const int wm = w & 3, wn = w >> 2;
    const int m0 = blockIdx.y * 128, n0 = blockIdx.x * 128;

    const __nv_bfloat16* srcs[4] = { Ah, Al, Bh, Bl };

    float acc[2][8][4];
    #pragma unroll
    for (int i = 0; i < 2; i++)
        #pragma unroll
        for (int j = 0; j < 8; j++)
            #pragma unroll
            for (int q = 0; q < 4; q++) acc[i][j][q] = 0.f;

    // precomputed lane pieces for loads
    const int ld_rowA = wm*32 + (lane & 15);              // + mf*16
    const int ld_kA   = ((lane >> 4) & 1) * 16;           // byte offset + ks*32
    const int ld_rowB = wn*64 + (lane & 7) + ((lane >> 4) & 1) * 8;   // + np*16
    const int ld_kB   = ((lane >> 3) & 1) * 16;           // byte offset + ks*32

    #define ISSUE_LOAD(cidx) do { \
        const int _s = (cidx) & 1; \
        const int _k0 = (cidx) * BK_; \
        const uint32_t _sbase = sb + _s * GSTAGE; \
        _Pragma("unroll") \
        for (int u = 0; u < 16; u++) { \
            int idx = u * 256 + t; \
            int tensor = idx >> 10; \
            int rem = idx & 1023; \
            int row = rem >> 3, cc = rem & 7; \
            int rbase = (tensor < 2) ? m0 : n0; \
            const __nv_bfloat16* g = srcs[tensor] + (size_t)(rbase + row) * C_ + _k0 + cc * 8; \
            cp_async16(_sbase + tensor * TSIZE + row * TSTRIDE + cc * 16, g); \
        } \
        asm volatile("cp.async.commit_group;" ::: "memory"); \
    } while (0)

    ISSUE_LOAD(0);

    for (int c = 0; c < 16; c++) {
        if (c + 1 < 16) {
            ISSUE_LOAD(c + 1);
            asm volatile("cp.async.wait_group 1;" ::: "memory");
        } else {
            asm volatile("cp.async.wait_group 0;" ::: "memory");
        }
        __syncthreads();

        const uint32_t sbase = sb + (c & 1) * GSTAGE;
        #pragma unroll
        for (int ks = 0; ks < 4; ks++) {
            uint32_t ah[2][4], al[2][4];
            #pragma unroll
            for (int mf = 0; mf < 2; mf++) {
                uint32_t addr = sbase + (ld_rowA + mf*16) * TSTRIDE + ks*32 + ld_kA;
                ldm_x4(ah[mf], addr);
                ldm_x4(al[mf], addr + TSIZE);
            }
            uint32_t bh[8][2], bl[8][2];
            #pragma unroll
            for (int np = 0; np < 4; np++) {
                uint32_t addr = sbase + 2*TSIZE + (ld_rowB + np*16) * TSTRIDE + ks*32 + ld_kB;
                uint32_t r[4];
                ldm_x4(r, addr);
                bh[np*2][0] = r[0]; bh[np*2][1] = r[1];
                bh[np*2+1][0] = r[2]; bh[np*2+1][1] = r[3];
                ldm_x4(r, addr + TSIZE);
                bl[np*2][0] = r[0]; bl[np*2][1] = r[1];
                bl[np*2+1][0] = r[2]; bl[np*2+1][1] = r[3];
            }
            #pragma unroll
            for (int mf = 0; mf < 2; mf++)
                #pragma unroll
                for (int nf = 0; nf < 8; nf++) {
                    mma_bf16(acc[mf][nf], ah[mf], bh[nf]);
                    mma_bf16(acc[mf][nf], ah[mf], bl[nf]);
                    mma_bf16(acc[mf][nf], al[mf], bh[nf]);
                }
        }
        __syncthreads();
    }

    // epilogue: acc[mf][nf] rows = wm*32+mf*16+lane/4 (+8); cols = wn*64+nf*8+(lane%4)*2
    #pragma unroll
    for (int mf = 0; mf < 2; mf++) {
        int row = m0 + wm*32 + mf*16 + (lane >> 2);
        #pragma unroll
        for (int nf = 0; nf < 8; nf++) {
            int col = n0 + wn*64 + nf*8 + (lane & 3)*2;
            float2 v0 = { acc[mf][nf][0], acc[mf][nf][1] };
            float2 v1 = { acc[mf][nf][2], acc[mf][nf][3] };
            if (SILU) {
                v0.x = v0.x / (1.f + expf(-v0.x));
                v0.y = v0.y / (1.f + expf(-v0.y));
                v1.x = v1.x / (1.f + expf(-v1.x));
                v1.y = v1.y / (1.f + expf(-v1.y));
            }
            *(float2*)&Cout[(size_t)row * C_ + col]       = v0;
            *(float2*)&Cout[(size_t)(row + 8) * C_ + col] = v1;
        }
    }
    #undef ISSUE_LOAD
}

// ---------------- rmsnorm(d=64) + RoPE (pos = head index!) + transpose ----------------
__global__ void normrope_kernel(const float* __restrict__ qn_w, const float* __restrict__ kn_w) {
    int gw   = blockIdx.x * (blockDim.x >> 5) + (threadIdx.x >> 5);   // 0..65535
    int lane = threadIdx.x & 31;
    int j  = gw & 1;
    int h  = (gw >> 1) & 7;
    int i  = (gw >> 4) & 511;
    int b  = (gw >> 13) & 3;
    int qk = (gw >> 15) & 1;

    const float* src = (qk ? g_k : g_q) + ((size_t)(b * R_ + i) * C_ + h * 128 + j * 64);
    const float* wv  = qk ? kn_w : qn_w;

    float x1 = src[lane], x2 = src[lane + 32];
    float ss = warp_sum(x1*x1 + x2*x2);
    float inv = 1.0f / sqrtf(ss * (1.0f / 64.0f) + EPS_);
    float n1 = x1 * inv * wv[lane];
    float n2 = x2 * inv * wv[lane + 32];

    float freq = expf(-(float)lane * (9.210340371976184f / 32.0f));
    float s, c;
    sincosf((float)h * freq, &s, &c);

    float* dst = (qk ? (j ? g_k2 : g_k1) : (j ? g_q2 : g_q1))
               + (size_t)((b * H_ + h) * R_ + i) * D_;
    dst[lane]      = n1 * c - n2 * s;
    dst[lane + 32] = n1 * s + n2 * c;
}

// ---------------- differential attention ----------------
__global__ __launch_bounds__(512, 1) void attn_kernel() {
    __shared__ float sKV[2 * 64 * 68];
    __shared__ float sQ1[16][64];
    __shared__ float sQ2[16][64];

    const int b = blockIdx.z, h = blockIdx.y;
    const int bh = b * H_ + h;
    const int w = threadIdx.x >> 5, lane = threadIdx.x & 31;
    const int qrow = blockIdx.x * 16 + w;

    {
        int idx = threadIdx.x;
        int tensor = idx >> 8;
        int rem = idx & 255;
        int row = rem >> 4, c4 = (rem & 15) * 4;
        size_t src = (size_t)(bh * R_ + blockIdx.x * 16 + row) * D_ + c4;
        float4 v = tensor ? *(const float4*)&g_q2[src] : *(const float4*)&g_q1[src];
        if (tensor) *(float4*)&sQ2[row][c4] = v;
        else        *(float4*)&sQ1[row][c4] = v;
    }

    float p1[16], p2[16];

    #pragma unroll
    for (int kt = 0; kt < 8; kt++) {
        __syncthreads();
        #pragma unroll
        for (int u = 0; u < 2; u++) {
            int idx = threadIdx.x + u * 512;
            int row = idx >> 4, c4 = (idx & 15) * 4;
            size_t src = (size_t)(bh * R_ + kt * 64 + row) * D_ + c4;
            *(float4*)&sKV[row * 68 + c4]           = *(const float4*)&g_k1[src];
            *(float4*)&sKV[64 * 68 + row * 68 + c4] = *(const float4*)&g_k2[src];
        }
        __syncthreads();

        float d1a = 0.f, d1b = 0.f, d2a = 0.f, d2b = 0.f;
        #pragma unroll
        for (int c4 = 0; c4 < 64; c4 += 4) {
            float4 Q1 = *(const float4*)&sQ1[w][c4];
            float4 Q2 = *(const float4*)&sQ2[w][c4];
            float4 A1 = *(const float4*)&sKV[lane * 68 + c4];
            float4 B1 = *(const float4*)&sKV[(lane + 32) * 68 + c4];
            float4 A2 = *(const float4*)&sKV[64 * 68 + lane * 68 + c4];
            float4 B2 = *(const float4*)&sKV[64 * 68 + (lane + 32) * 68 + c4];
            d1a += Q1.x*A1.x + Q1.y*A1.y + Q1.z*A1.z + Q1.w*A1.w;
            d1b += Q1.x*B1.x + Q1.y*B1.y + Q1.z*B1.z + Q1.w*B1.w;
            d2a += Q2.x*A2.x + Q2.y*A2.y + Q2.z*A2.z + Q2.w*A2.w;
            d2b += Q2.x*B2.x + Q2.y*B2.y + Q2.z*B2.z + Q2.w*B2.w;
        }
        p1[2*kt]   = d1a * 0.125f;  p1[2*kt+1] = d1b * 0.125f;
        p2[2*kt]   = d2a * 0.125f;  p2[2*kt+1] = d2b * 0.125f;
    }

    float m1 = -1e30f, m2 = -1e30f;
    #pragma unroll
    for (int s = 0; s < 16; s++) { m1 = fmaxf(m1, p1[s]); m2 = fmaxf(m2, p2[s]); }
    m1 = warp_max(m1);  m2 = warp_max(m2);
    float s1 = 0.f, s2 = 0.f;
    #pragma unroll
    for (int s = 0; s < 16; s++) {
        p1[s] = expf(p1[s] - m1);  s1 += p1[s];
        p2[s] = expf(p2[s] - m2);  s2 += p2[s];
    }
    s1 = warp_sum(s1);  s2 = warp_sum(s2);
    float inv1 = 1.0f / s1;
    float inv2 = g_lam / s2;
    #pragma unroll
    for (int s = 0; s < 16; s++) p1[s] = p1[s] * inv1 - p2[s] * inv2;

    float4 acc = make_float4(0.f, 0.f, 0.f, 0.f);
    #pragma unroll
    for (int kt = 0; kt < 8; kt++) {
        __syncthreads();
        #pragma unroll
        for (int u = 0; u < 4; u++) {
            int idx = threadIdx.x + u * 512;
            int row = idx >> 5, c4 = (idx & 31) * 4;
            *(float4*)&sKV[row * 128 + c4] =
                *(const float4*)&g_v[(size_t)(b * R_ + kt * 64 + row) * C_ + h * 128 + c4];
        }
        __syncthreads();
        #pragma unroll
        for (int ss = 0; ss < 2; ss++) {
            float pown = p1[2*kt + ss];
            #pragma unroll
            for (int src = 0; src < 32; src++) {
                float p = __shfl_sync(0xffffffffu, pown, src);
                float4 V = *(const float4*)&sKV[(ss * 32 + src) * 128 + 4 * lane];
                acc.x += p * V.x;  acc.y += p * V.y;
                acc.z += p * V.z;  acc.w += p * V.w;
            }
        }
    }
    *(float4*)&g_diff[(size_t)(b * R_ + qrow) * C_ + h * 128 + 4 * lane] = acc;
}

// ---------------- head rmsnorm (2d=128) * 0.2, fused bf16 split ----------------
__global__ void headnorm_kernel(const float* __restrict__ hw) {
    int gw   = blockIdx.x * 4 + (threadIdx.x >> 5);   // 0..16383
    int lane = threadIdx.x & 31;
    int m = gw >> 3, h = gw & 7;
    size_t base = (size_t)m * C_ + h * 128 + 4 * lane;
    float4 v = *(const float4*)&g_diff[base];
    float ss = warp_sum(v.x*v.x + v.y*v.y + v.z*v.z + v.w*v.w);
    float inv = 0.2f / sqrtf(ss * (1.0f / 128.0f) + EPS_);
    float4 wv = *(const float4*)&hw[4 * lane];
    float4 o = { v.x*inv*wv.x, v.y*inv*wv.y, v.z*inv*wv.z, v.w*inv*wv.w };
    split4(o, g_dh, g_dl, base);
}

// ---------------- upsample 512 -> 4096 ----------------
__global__ void upsample_kernel(float* __restrict__ out, const float* __restrict__ low) {
    int idx = blockIdx.x * blockDim.x + threadIdx.x;     // < 4194304
    int c = (idx & 255) * 4;
    int t = idx >> 8;                                    // 0..16383
    int j = t & 4095, b = t >> 12;
    float coord = fminf(fmaxf(0.125f * (float)j - 0.4375f, 0.0f), 511.0f);
    int lo = (int)coord;
    int hi = min(lo + 1, 511);
    float wgt = coord - (float)lo;
    const float* lb = low + (size_t)b * R_ * C_;
    float4 a  = *(const float4*)&lb[(size_t)lo * C_ + c];
    float4 bb = *(const float4*)&lb[(size_t)hi * C_ + c];
    float4 o = { a.x*(1.f-wgt) + bb.x*wgt, a.y*(1.f-wgt) + bb.y*wgt,
                 a.z*(1.f-wgt) + bb.z*wgt, a.w*(1.f-wgt) + bb.w*wgt };
    *(float4*)&out[(size_t)(b * L_ + j) * C_ + c] = o;
}

// ---------------- launch ----------------
extern "C" void kernel_launch(void* const* d_in, const int* in_sizes, int n_in,
                              void* d_out, int out_size) {
    (void)in_sizes; (void)n_in; (void)out_size;
    const float* x   = (const float*)d_in[0];
    const float* W[4] = { (const float*)d_in[1], (const float*)d_in[2],
                          (const float*)d_in[3], (const float*)d_in[4] };  // Wq,Wk,Wv,Wo
    const float* qn  = (const float*)d_in[5];
    const float* kn  = (const float*)d_in[6];
    const float* hw  = (const float*)d_in[7];
    const float* lq1 = (const float*)d_in[8];
    const float* lk1 = (const float*)d_in[9];
    const float* lq2 = (const float*)d_in[10];
    const float* lk2 = (const float*)d_in[11];

    float* out     = (float*)d_out;
    float* out_low = out + FULL_ELEMS;

    float *p_q, *p_k, *p_v;
    cudaGetSymbolAddress((void**)&p_q, g_q);
    cudaGetSymbolAddress((void**)&p_k, g_k);
    cudaGetSymbolAddress((void**)&p_v, g_v);
    __nv_bfloat16 *p_xdh, *p_xdl, *p_dh, *p_dl, *p_wh, *p_wl;
    cudaGetSymbolAddress((void**)&p_xdh, g_xdh);
    cudaGetSymbolAddress((void**)&p_xdl, g_xdl);
    cudaGetSymbolAddress((void**)&p_dh,  g_dh);
    cudaGetSymbolAddress((void**)&p_dl,  g_dl);
    cudaGetSymbolAddress((void**)&p_wh,  g_wh);
    cudaGetSymbolAddress((void**)&p_wl,  g_wl);

    cudaFuncSetAttribute(gemm_tc<false>, cudaFuncAttributeMaxDynamicSharedMemorySize, GSM_TOTAL);
    cudaFuncSetAttribute(gemm_tc<true>,  cudaFuncAttributeMaxDynamicSharedMemorySize, GSM_TOTAL);

    lam_kernel<<<1, 32>>>(lq1, lk1, lq2, lk2);
    downsample_kernel<<<2048, 256>>>(x);
    for (int i = 0; i < 4; i++)
        split_kernel<<<1024, 256>>>(W[i], p_wh + (size_t)i * C_ * C_, p_wl + (size_t)i * C_ * C_);

    dim3 ggrid(C_ / 128, M_ / 128);   // (8, 16)
    gemm_tc<false><<<ggrid, 256, GSM_TOTAL>>>(p_xdh, p_xdl, p_wh + 0*(size_t)C_*C_, p_wl + 0*(size_t)C_*C_, p_q);
    gemm_tc<false><<<ggrid, 256, GSM_TOTAL>>>(p_xdh, p_xdl, p_wh + 1*(size_t)C_*C_, p_wl + 1*(size_t)C_*C_, p_k);
    gemm_tc<false><<<ggrid, 256, GSM_TOTAL>>>(p_xdh, p_xdl, p_wh + 2*(size_t)C_*C_, p_wl + 2*(size_t)C_*C_, p_v);

    normrope_kernel<<<16384, 128>>>(qn, kn);
    attn_kernel<<<dim3(R_ / 16, H_, B_), 512>>>();
    headnorm_kernel<<<4096, 128>>>(hw);

    gemm_tc<true><<<ggrid, 256, GSM_TOTAL>>>(p_dh, p_dl, p_wh + 3*(size_t)C_*C_, p_wl + 3*(size_t)C_*C_, out_low);
    upsample_kernel<<<16384, 256>>>(out, out_low);
}

// round 12
// speedup vs baseline: 1.0005x; 1.0005x over previous
#include <cuda_runtime.h>
#include <cuda_bf16.h>
#include <math.h>
#include <stdint.h>

// ---------------- problem constants ----------------
#define B_  4
#define L_  4096
#define C_  1024
#define H_  8
#define D_  64      // C / (2H)
#define R_  512     // int(L^0.75)
#define M_  (B_*R_) // 2048 GEMM rows
#define FULL_ELEMS (B_*L_*C_)   // 16777216
#define LAMBDA_INIT 0.8f
#define EPS_ 1e-6f

// ---------------- device scratch (no allocs allowed) ----------------
__device__ float g_q   [M_*C_];
__device__ float g_k   [M_*C_];
__device__ float g_v   [M_*C_];
__device__ float g_q1  [B_*H_*R_*D_];
__device__ float g_q2  [B_*H_*R_*D_];
__device__ float g_k1  [B_*H_*R_*D_];
__device__ float g_k2  [B_*H_*R_*D_];
__device__ float g_diff[M_*C_];
__device__ float g_lam;

// bf16 hi/lo split operands for tensor-core GEMMs
__device__ __nv_bfloat16 g_xdh[M_*C_], g_xdl[M_*C_];       // downsampled x
__device__ __nv_bfloat16 g_dh [M_*C_], g_dl [M_*C_];       // head-normed diff
__device__ __nv_bfloat16 g_wh [4][C_*C_], g_wl[4][C_*C_];  // Wq,Wk,Wv,Wo

// ---------------- warp helpers ----------------
__device__ __forceinline__ float warp_sum(float v) {
    #pragma unroll
    for (int o = 16; o > 0; o >>= 1) v += __shfl_xor_sync(0xffffffffu, v, o);
    return v;
}
__device__ __forceinline__ float warp_max(float v) {
    #pragma unroll
    for (int o = 16; o > 0; o >>= 1) v = fmaxf(v, __shfl_xor_sync(0xffffffffu, v, o));
    return v;
}

// ---------------- PTX helpers (HMMA path: valid on compute_103 PTX target) ----
__device__ __forceinline__ uint32_t smem_u32(const void* p) {
    uint32_t a;
    asm("{ .reg .u64 t; cvta.to.shared.u64 t, %1; cvt.u32.u64 %0, t; }" : "=r"(a) : "l"(p));
    return a;
}
__device__ __forceinline__ void cp_async16(uint32_t dst, const void* src) {
    asm volatile("cp.async.cg.shared.global [%0], [%1], 16;" :: "r"(dst), "l"(src) : "memory");
}
__device__ __forceinline__ void ldm_x4(uint32_t* r, uint32_t addr) {
    asm volatile("ldmatrix.sync.aligned.m8n8.x4.shared.b16 {%0,%1,%2,%3}, [%4];"
                 : "=r"(r[0]), "=r"(r[1]), "=r"(r[2]), "=r"(r[3]) : "r"(addr));
}
__device__ __forceinline__ void mma_bf16(float* c, const uint32_t* a, const uint32_t* b) {
    asm volatile(
        "mma.sync.aligned.m16n8k16.row.col.f32.bf16.bf16.f32 "
        "{%0,%1,%2,%3}, {%4,%5,%6,%7}, {%8,%9}, {%0,%1,%2,%3};"
        : "+f"(c[0]), "+f"(c[1]), "+f"(c[2]), "+f"(c[3])
        : "r"(a[0]), "r"(a[1]), "r"(a[2]), "r"(a[3]), "r"(b[0]), "r"(b[1]));
}

// ---------------- fp32 -> (bf16 hi, bf16 lo) split ----------------
__device__ __forceinline__ void split4(float4 o, __nv_bfloat16* hi, __nv_bfloat16* lo, size_t base) {
    __nv_bfloat16 h0 = __float2bfloat16(o.x), h1 = __float2bfloat16(o.y);
    __nv_bfloat16 h2 = __float2bfloat16(o.z), h3 = __float2bfloat16(o.w);
    __nv_bfloat16 l0 = __float2bfloat16(o.x - __bfloat162float(h0));
    __nv_bfloat16 l1 = __float2bfloat16(o.y - __bfloat162float(h1));
    __nv_bfloat16 l2 = __float2bfloat16(o.z - __bfloat162float(h2));
    __nv_bfloat16 l3 = __float2bfloat16(o.w - __bfloat162float(h3));
    __nv_bfloat162 ha; ha.x = h0; ha.y = h1;
    __nv_bfloat162 hb; hb.x = h2; hb.y = h3;
    __nv_bfloat162 la; la.x = l0; la.y = l1;
    __nv_bfloat162 lb; lb.x = l2; lb.y = l3;
    *(__nv_bfloat162*)&hi[base]     = ha;
    *(__nv_bfloat162*)&hi[base + 2] = hb;
    *(__nv_bfloat162*)&lo[base]     = la;
    *(__nv_bfloat162*)&lo[base + 2] = lb;
}

__global__ void split_kernel(const float* __restrict__ x,
                             __nv_bfloat16* __restrict__ hi, __nv_bfloat16* __restrict__ lo) {
    int i = blockIdx.x * blockDim.x + threadIdx.x;    // n/4 threads
    float4 v = *(const float4*)&x[(size_t)i * 4];
    split4(v, hi, lo, (size_t)i * 4);
}

// ---------------- lambda scalar ----------------
__global__ void lam_kernel(const float* __restrict__ lq1, const float* __restrict__ lk1,
                           const float* __restrict__ lq2, const float* __restrict__ lk2) {
    int l = threadIdx.x;
    float s1 = lq1[l]*lk1[l] + lq1[l+32]*lk1[l+32];
    float s2 = lq2[l]*lk2[l] + lq2[l+32]*lk2[l+32];
    s1 = warp_sum(s1);
    s2 = warp_sum(s2);
    if (l == 0) g_lam = expf(s1) - expf(s2) + LAMBDA_INIT;
}

// ---------------- downsample + split: xd = 0.5*(x[8i+3] + x[8i+4]) ----------------
__global__ void downsample_kernel(const float* __restrict__ x) {
    int idx = blockIdx.x * blockDim.x + threadIdx.x;         // < 2048*256
    int c  = (idx & 255) * 4;
    int m  = idx >> 8;                                       // 0..2047
    int b  = m >> 9, i = m & 511;
    size_t src = ((size_t)b * L_ + 8 * i + 3) * C_ + c;
    float4 a  = *(const float4*)&x[src];
    float4 bb = *(const float4*)&x[src + C_];
    float4 o = { 0.5f*(a.x+bb.x), 0.5f*(a.y+bb.y), 0.5f*(a.z+bb.z), 0.5f*(a.w+bb.w) };
    split4(o, g_xdh, g_xdl, (size_t)m * C_ + c);
}

// ---------------- HMMA split-bf16 GEMM ----------------
// C[m,n] = sum_k A[m,k]*B[n,k], fp32 accum, 3 MMAs: Ah*Bh + Ah*Bl + Al*Bh.
// Block tile 128x128, 8 warps (warp tile 32x64), K-chunk 64, double-buffered cp.async.
#define BK_      64
#define TSTRIDE  144                   // bytes per SMEM row (128 data + 16 pad)
#define TSIZE    (128 * TSTRIDE)       // 18432 per tensor
#define GSTAGE   (4 * TSIZE)           // Ah, Al, Bh, Bl
#define GSM_TOTAL (2 * GSTAGE)         // 147456

template<bool SILU>
__global__ __launch_bounds__(256, 1) void gemm_tc(
    const __nv_bfloat16* __restrict__ Ah, const __nv_bfloat16* __restrict__ Al,
    const __nv_bfloat16* __restrict__ Bh, const __nv_bfloat16* __restrict__ Bl,
    float* __restrict__ Cout)
{
    extern __shared__ char smc[];
    const uint32_t sb = smem_u32(smc);
    const int t = threadIdx.x, w = t >> 5, lane = t & 31;
    const int wm = w & 3, wn = w >> 2;
    const int m0 = blockIdx.y * 128, n0 = blockIdx.x * 128;

    const __nv_bfloat16* srcs[4] = { Ah, Al, Bh, Bl };

    float acc[2][8][4];
    #pragma unroll
    for (int i = 0; i < 2; i++)
        #pragma unroll
        for (int j = 0; j < 8; j++)
            #pragma unroll
            for (int q = 0; q < 4; q++) acc[i][j][q] = 0.f;

    // precomputed lane pieces for loads
    const int ld_rowA = wm*32 + (lane & 15);              // + mf*16
    const int ld_kA   = ((lane >> 4) & 1) * 16;           // byte offset + ks*32
    const int ld_rowB = wn*64 + (lane & 7) + ((lane >> 4) & 1) * 8;   // + np*16
    const int ld_kB   = ((lane >> 3) & 1) * 16;           // byte offset + ks*32

    #define ISSUE_LOAD(cidx) do { \
        const int _s = (cidx) & 1; \
        const int _k0 = (cidx) * BK_; \
        const uint32_t _sbase = sb + _s * GSTAGE; \
        _Pragma("unroll") \
        for (int u = 0; u < 16; u++) { \
            int idx = u * 256 + t; \
            int tensor = idx >> 10; \
            int rem = idx & 1023; \
            int row = rem >> 3, cc = rem & 7; \
            int rbase = (tensor < 2) ? m0 : n0; \
            const __nv_bfloat16* g = srcs[tensor] + (size_t)(rbase + row) * C_ + _k0 + cc * 8; \
            cp_async16(_sbase + tensor * TSIZE + row * TSTRIDE + cc * 16, g); \
        } \
        asm volatile("cp.async.commit_group;" ::: "memory"); \
    } while (0)

    ISSUE_LOAD(0);

    for (int c = 0; c < 16; c++) {
        if (c + 1 < 16) {
            ISSUE_LOAD(c + 1);
            asm volatile("cp.async.wait_group 1;" ::: "memory");
        } else {
            asm volatile("cp.async.wait_group 0;" ::: "memory");
        }
        __syncthreads();

        const uint32_t sbase = sb + (c & 1) * GSTAGE;
        #pragma unroll
        for (int ks = 0; ks < 4; ks++) {
            uint32_t ah[2][4], al[2][4];
            #pragma unroll
            for (int mf = 0; mf < 2; mf++) {
                uint32_t addr = sbase + (ld_rowA + mf*16) * TSTRIDE + ks*32 + ld_kA;
                ldm_x4(ah[mf], addr);
                ldm_x4(al[mf], addr + TSIZE);
            }
            uint32_t bh[8][2], bl[8][2];
            #pragma unroll
            for (int np = 0; np < 4; np++) {
                uint32_t addr = sbase + 2*TSIZE + (ld_rowB + np*16) * TSTRIDE + ks*32 + ld_kB;
                uint32_t r[4];
                ldm_x4(r, addr);
                bh[np*2][0] = r[0]; bh[np*2][1] = r[1];
                bh[np*2+1][0] = r[2]; bh[np*2+1][1] = r[3];
                ldm_x4(r, addr + TSIZE);
                bl[np*2][0] = r[0]; bl[np*2][1] = r[1];
                bl[np*2+1][0] = r[2]; bl[np*2+1][1] = r[3];
            }
            #pragma unroll
            for (int mf = 0; mf < 2; mf++)
                #pragma unroll
                for (int nf = 0; nf < 8; nf++) {
                    mma_bf16(acc[mf][nf], ah[mf], bh[nf]);
                    mma_bf16(acc[mf][nf], ah[mf], bl[nf]);
                    mma_bf16(acc[mf][nf], al[mf], bh[nf]);
                }
        }
        __syncthreads();
    }

    // epilogue: acc[mf][nf] rows = wm*32+mf*16+lane/4 (+8); cols = wn*64+nf*8+(lane%4)*2
    #pragma unroll
    for (int mf = 0; mf < 2; mf++) {
        int row = m0 + wm*32 + mf*16 + (lane >> 2);
        #pragma unroll
        for (int nf = 0; nf < 8; nf++) {
            int col = n0 + wn*64 + nf*8 + (lane & 3)*2;
            float2 v0 = { acc[mf][nf][0], acc[mf][nf][1] };
            float2 v1 = { acc[mf][nf][2], acc[mf][nf][3] };
            if (SILU) {
                v0.x = v0.x / (1.f + expf(-v0.x));
                v0.y = v0.y / (1.f + expf(-v0.y));
                v1.x = v1.x / (1.f + expf(-v1.x));
                v1.y = v1.y / (1.f + expf(-v1.y));
            }
            *(float2*)&Cout[(size_t)row * C_ + col]       = v0;
            *(float2*)&Cout[(size_t)(row + 8) * C_ + col] = v1;
        }
    }
    #undef ISSUE_LOAD
}

// ---------------- rmsnorm(d=64) + RoPE (pos = head index!) + transpose ----------------
__global__ void normrope_kernel(const float* __restrict__ qn_w, const float* __restrict__ kn_w) {
    int gw   = blockIdx.x * (blockDim.x >> 5) + (threadIdx.x >> 5);   // 0..65535
    int lane = threadIdx.x & 31;
    int j  = gw & 1;
    int h  = (gw >> 1) & 7;
    int i  = (gw >> 4) & 511;
    int b  = (gw >> 13) & 3;
    int qk = (gw >> 15) & 1;

    const float* src = (qk ? g_k : g_q) + ((size_t)(b * R_ + i) * C_ + h * 128 + j * 64);
    const float* wv  = qk ? kn_w : qn_w;

    float x1 = src[lane], x2 = src[lane + 32];
    float ss = warp_sum(x1*x1 + x2*x2);
    float inv = 1.0f / sqrtf(ss * (1.0f / 64.0f) + EPS_);
    float n1 = x1 * inv * wv[lane];
    float n2 = x2 * inv * wv[lane + 32];

    float freq = expf(-(float)lane * (9.210340371976184f / 32.0f));
    float s, c;
    sincosf((float)h * freq, &s, &c);

    float* dst = (qk ? (j ? g_k2 : g_k1) : (j ? g_q2 : g_q1))
               + (size_t)((b * H_ + h) * R_ + i) * D_;
    dst[lane]      = n1 * c - n2 * s;
    dst[lane + 32] = n1 * s + n2 * c;
}

// ---------------- differential attention ----------------
__global__ __launch_bounds__(512, 1) void attn_kernel() {
    __shared__ float sKV[2 * 64 * 68];
    __shared__ float sQ1[16][64];
    __shared__ float sQ2[16][64];

    const int b = blockIdx.z, h = blockIdx.y;
    const int bh = b * H_ + h;
    const int w = threadIdx.x >> 5, lane = threadIdx.x & 31;
    const int qrow = blockIdx.x * 16 + w;

    {
        int idx = threadIdx.x;
        int tensor = idx >> 8;
        int rem = idx & 255;
        int row = rem >> 4, c4 = (rem & 15) * 4;
        size_t src = (size_t)(bh * R_ + blockIdx.x * 16 + row) * D_ + c4;
        float4 v = tensor ? *(const float4*)&g_q2[src] : *(const float4*)&g_q1[src];
        if (tensor) *(float4*)&sQ2[row][c4] = v;
        else        *(float4*)&sQ1[row][c4] = v;
    }

    float p1[16], p2[16];

    #pragma unroll
    for (int kt = 0; kt < 8; kt++) {
        __syncthreads();
        #pragma unroll
        for (int u = 0; u < 2; u++) {
            int idx = threadIdx.x + u * 512;
            int row = idx >> 4, c4 = (idx & 15) * 4;
            size_t src = (size_t)(bh * R_ + kt * 64 + row) * D_ + c4;
            *(float4*)&sKV[row * 68 + c4]           = *(const float4*)&g_k1[src];
            *(float4*)&sKV[64 * 68 + row * 68 + c4] = *(const float4*)&g_k2[src];
        }
        __syncthreads();

        float d1a = 0.f, d1b = 0.f, d2a = 0.f, d2b = 0.f;
        #pragma unroll
        for (int c4 = 0; c4 < 64; c4 += 4) {
            float4 Q1 = *(const float4*)&sQ1[w][c4];
            float4 Q2 = *(const float4*)&sQ2[w][c4];
            float4 A1 = *(const float4*)&sKV[lane * 68 + c4];
            float4 B1 = *(const float4*)&sKV[(lane + 32) * 68 + c4];
            float4 A2 = *(const float4*)&sKV[64 * 68 + lane * 68 + c4];
            float4 B2 = *(const float4*)&sKV[64 * 68 + (lane + 32) * 68 + c4];
            d1a += Q1.x*A1.x + Q1.y*A1.y + Q1.z*A1.z + Q1.w*A1.w;
            d1b += Q1.x*B1.x + Q1.y*B1.y + Q1.z*B1.z + Q1.w*B1.w;
            d2a += Q2.x*A2.x + Q2.y*A2.y + Q2.z*A2.z + Q2.w*A2.w;
            d2b += Q2.x*B2.x + Q2.y*B2.y + Q2.z*B2.z + Q2.w*B2.w;
        }
        p1[2*kt]   = d1a * 0.125f;  p1[2*kt+1] = d1b * 0.125f;
        p2[2*kt]   = d2a * 0.125f;  p2[2*kt+1] = d2b * 0.125f;
    }

    float m1 = -1e30f, m2 = -1e30f;
    #pragma unroll
    for (int s = 0; s < 16; s++) { m1 = fmaxf(m1, p1[s]); m2 = fmaxf(m2, p2[s]); }
    m1 = warp_max(m1);  m2 = warp_max(m2);
    float s1 = 0.f, s2 = 0.f;
    #pragma unroll
    for (int s = 0; s < 16; s++) {
        p1[s] = expf(p1[s] - m1);  s1 += p1[s];
        p2[s] = expf(p2[s] - m2);  s2 += p2[s];
    }
    s1 = warp_sum(s1);  s2 = warp_sum(s2);
    float inv1 = 1.0f / s1;
    float inv2 = g_lam / s2;
    #pragma unroll
    for (int s = 0; s < 16; s++) p1[s] = p1[s] * inv1 - p2[s] * inv2;

    float4 acc = make_float4(0.f, 0.f, 0.f, 0.f);
    #pragma unroll
    for (int kt = 0; kt < 8; kt++) {
        __syncthreads();
        #pragma unroll
        for (int u = 0; u < 4; u++) {
            int idx = threadIdx.x + u * 512;
            int row = idx >> 5, c4 = (idx & 31) * 4;
            *(float4*)&sKV[row * 128 + c4] =
                *(const float4*)&g_v[(size_t)(b * R_ + kt * 64 + row) * C_ + h * 128 + c4];
        }
        __syncthreads();
        #pragma unroll
        for (int ss = 0; ss < 2; ss++) {
            float pown = p1[2*kt + ss];
            #pragma unroll
            for (int src = 0; src < 32; src++) {
                float p = __shfl_sync(0xffffffffu, pown, src);
                float4 V = *(const float4*)&sKV[(ss * 32 + src) * 128 + 4 * lane];
                acc.x += p * V.x;  acc.y += p * V.y;
                acc.z += p * V.z;  acc.w += p * V.w;
            }
        }
    }
    *(float4*)&g_diff[(size_t)(b * R_ + qrow) * C_ + h * 128 + 4 * lane] = acc;
}

// ---------------- head rmsnorm (2d=128) * 0.2, fused bf16 split ----------------
__global__ void headnorm_kernel(const float* __restrict__ hw) {
    int gw   = blockIdx.x * 4 + (threadIdx.x >> 5);   // 0..16383
    int lane = threadIdx.x & 31;
    int m = gw >> 3, h = gw & 7;
    size_t base = (size_t)m * C_ + h * 128 + 4 * lane;
    float4 v = *(const float4*)&g_diff[base];
    float ss = warp_sum(v.x*v.x + v.y*v.y + v.z*v.z + v.w*v.w);
    float inv = 0.2f / sqrtf(ss * (1.0f / 128.0f) + EPS_);
    float4 wv = *(const float4*)&hw[4 * lane];
    float4 o = { v.x*inv*wv.x, v.y*inv*wv.y, v.z*inv*wv.z, v.w*inv*wv.w };
    split4(o, g_dh, g_dl, base);
}

// ---------------- upsample 512 -> 4096 ----------------
__global__ void upsample_kernel(float* __restrict__ out, const float* __restrict__ low) {
    int idx = blockIdx.x * blockDim.x + threadIdx.x;     // < 4194304
    int c = (idx & 255) * 4;
    int t = idx >> 8;                                    // 0..16383
    int j = t & 4095, b = t >> 12;
    float coord = fminf(fmaxf(0.125f * (float)j - 0.4375f, 0.0f), 511.0f);
    int lo = (int)coord;
    int hi = min(lo + 1, 511);
    float wgt = coord - (float)lo;
    const float* lb = low + (size_t)b * R_ * C_;
    float4 a  = *(const float4*)&lb[(size_t)lo * C_ + c];
    float4 bb = *(const float4*)&lb[(size_t)hi * C_ + c];
    float4 o = { a.x*(1.f-wgt) + bb.x*wgt, a.y*(1.f-wgt) + bb.y*wgt,
                 a.z*(1.f-wgt) + bb.z*wgt, a.w*(1.f-wgt) + bb.w*wgt };
    *(float4*)&out[(size_t)(b * L_ + j) * C_ + c] = o;
}

// ---------------- launch ----------------
extern "C" void kernel_launch(void* const* d_in, const int* in_sizes, int n_in,
                              void* d_out, int out_size) {
    (void)in_sizes; (void)n_in; (void)out_size;
    const float* x   = (const float*)d_in[0];
    const float* W[4] = { (const float*)d_in[1], (const float*)d_in[2],
                          (const float*)d_in[3], (const float*)d_in[4] };  // Wq,Wk,Wv,Wo
    const float* qn  = (const float*)d_in[5];
    const float* kn  = (const float*)d_in[6];
    const float* hw  = (const float*)d_in[7];
    const float* lq1 = (const float*)d_in[8];
    const float* lk1 = (const float*)d_in[9];
    const float* lq2 = (const float*)d_in[10];
    const float* lk2 = (const float*)d_in[11];

    float* out     = (float*)d_out;
    float* out_low = out + FULL_ELEMS;

    float *p_q, *p_k, *p_v;
    cudaGetSymbolAddress((void**)&p_q, g_q);
    cudaGetSymbolAddress((void**)&p_k, g_k);
    cudaGetSymbolAddress((void**)&p_v, g_v);
    __nv_bfloat16 *p_xdh, *p_xdl, *p_dh, *p_dl, *p_wh, *p_wl;
    cudaGetSymbolAddress((void**)&p_xdh, g_xdh);
    cudaGetSymbolAddress((void**)&p_xdl, g_xdl);
    cudaGetSymbolAddress((void**)&p_dh,  g_dh);
    cudaGetSymbolAddress((void**)&p_dl,  g_dl);
    cudaGetSymbolAddress((void**)&p_wh,  g_wh);
    cudaGetSymbolAddress((void**)&p_wl,  g_wl);

    cudaFuncSetAttribute(gemm_tc<false>, cudaFuncAttributeMaxDynamicSharedMemorySize, GSM_TOTAL);
    cudaFuncSetAttribute(gemm_tc<true>,  cudaFuncAttributeMaxDynamicSharedMemorySize, GSM_TOTAL);

    lam_kernel<<<1, 32>>>(lq1, lk1, lq2, lk2);
    downsample_kernel<<<2048, 256>>>(x);
    for (int i = 0; i < 4; i++)
        split_kernel<<<1024, 256>>>(W[i], p_wh + (size_t)i * C_ * C_, p_wl + (size_t)i * C_ * C_);

    dim3 ggrid(C_ / 128, M_ / 128);   // (8, 16)
    gemm_tc<false><<<ggrid, 256, GSM_TOTAL>>>(p_xdh, p_xdl, p_wh + 0*(size_t)C_*C_, p_wl + 0*(size_t)C_*C_, p_q);
    gemm_tc<false><<<ggrid, 256, GSM_TOTAL>>>(p_xdh, p_xdl, p_wh + 1*(size_t)C_*C_, p_wl + 1*(size_t)C_*C_, p_k);
    gemm_tc<false><<<ggrid, 256, GSM_TOTAL>>>(p_xdh, p_xdl, p_wh + 2*(size_t)C_*C_, p_wl + 2*(size_t)C_*C_, p_v);

    normrope_kernel<<<16384, 128>>>(qn, kn);
    attn_kernel<<<dim3(R_ / 16, H_, B_), 512>>>();
    headnorm_kernel<<<4096, 128>>>(hw);

    gemm_tc<true><<<ggrid, 256, GSM_TOTAL>>>(p_dh, p_dl, p_wh + 3*(size_t)C_*C_, p_wl + 3*(size_t)C_*C_, out_low);
    upsample_kernel<<<16384, 256>>>(out, out_low);
}

// round 13
// speedup vs baseline: 1.6169x; 1.6161x over previous
#include <cuda_runtime.h>
#include <cuda_bf16.h>
#include <math.h>
#include <stdint.h>

// ---------------- problem constants ----------------
#define B_  4
#define L_  4096
#define C_  1024
#define H_  8
#define D_  64      // C / (2H)
#define R_  512     // int(L^0.75)
#define M_  (B_*R_) // 2048 GEMM rows
#define FULL_ELEMS (B_*L_*C_)   // 16777216
#define LAMBDA_INIT 0.8f
#define EPS_ 1e-6f

// ---------------- device scratch (no allocs allowed) ----------------
__device__ float g_q   [M_*C_];
__device__ float g_k   [M_*C_];
__device__ float g_v   [M_*C_];
__device__ float g_lam;

// bf16 hi/lo split operands for tensor-core GEMMs
__device__ __nv_bfloat16 g_xdh[M_*C_], g_xdl[M_*C_];       // downsampled x
__device__ __nv_bfloat16 g_dh [M_*C_], g_dl [M_*C_];       // head-normed diff
__device__ __nv_bfloat16 g_wh [4][C_*C_], g_wl[4][C_*C_];  // Wq,Wk,Wv,Wo

// bf16 hi/lo Q/K (normrope output, q pre-scaled by 0.125) [B*H][R][D]
__device__ __nv_bfloat16 g_q1h[B_*H_*R_*D_], g_q1l[B_*H_*R_*D_];
__device__ __nv_bfloat16 g_q2h[B_*H_*R_*D_], g_q2l[B_*H_*R_*D_];
__device__ __nv_bfloat16 g_k1h[B_*H_*R_*D_], g_k1l[B_*H_*R_*D_];
__device__ __nv_bfloat16 g_k2h[B_*H_*R_*D_], g_k2l[B_*H_*R_*D_];
// transposed V hi/lo: [B*H][dim 128][key 512]
__device__ __nv_bfloat16 g_vth[B_*H_*128*R_], g_vtl[B_*H_*128*R_];

// ---------------- warp helpers ----------------
__device__ __forceinline__ float warp_sum(float v) {
    #pragma unroll
    for (int o = 16; o > 0; o >>= 1) v += __shfl_xor_sync(0xffffffffu, v, o);
    return v;
}

// ---------------- PTX helpers (HMMA path: valid on compute_103 PTX target) ----
__device__ __forceinline__ uint32_t smem_u32(const void* p) {
    uint32_t a;
    asm("{ .reg .u64 t; cvta.to.shared.u64 t, %1; cvt.u32.u64 %0, t; }" : "=r"(a) : "l"(p));
    return a;
}
__device__ __forceinline__ void cp_async16(uint32_t dst, const void* src) {
    asm volatile("cp.async.cg.shared.global [%0], [%1], 16;" :: "r"(dst), "l"(src) : "memory");
}
__device__ __forceinline__ void ldm_x4(uint32_t* r, uint32_t addr) {
    asm volatile("ldmatrix.sync.aligned.m8n8.x4.shared.b16 {%0,%1,%2,%3}, [%4];"
                 : "=r"(r[0]), "=r"(r[1]), "=r"(r[2]), "=r"(r[3]) : "r"(addr));
}
__device__ __forceinline__ void mma_bf16(float* c, const uint32_t* a, const uint32_t* b) {
    asm volatile(
        "mma.sync.aligned.m16n8k16.row.col.f32.bf16.bf16.f32 "
        "{%0,%1,%2,%3}, {%4,%5,%6,%7}, {%8,%9}, {%0,%1,%2,%3};"
        : "+f"(c[0]), "+f"(c[1]), "+f"(c[2]), "+f"(c[3])
        : "r"(a[0]), "r"(a[1]), "r"(a[2]), "r"(a[3]), "r"(b[0]), "r"(b[1]));
}
// pack two floats into bf16x2: low half = lo, high half = hi
__device__ __forceinline__ uint32_t pack_bf16x2(float lo, float hi) {
    uint32_t r;
    asm("cvt.rn.bf16x2.f32 %0, %1, %2;" : "=r"(r) : "f"(hi), "f"(lo));
    return r;
}

// ---------------- fp32 -> (bf16 hi, bf16 lo) split ----------------
__device__ __forceinline__ void split4(float4 o, __nv_bfloat16* hi, __nv_bfloat16* lo, size_t base) {
    __nv_bfloat16 h0 = __float2bfloat16(o.x), h1 = __float2bfloat16(o.y);
    __nv_bfloat16 h2 = __float2bfloat16(o.z), h3 = __float2bfloat16(o.w);
    __nv_bfloat16 l0 = __float2bfloat16(o.x - __bfloat162float(h0));
    __nv_bfloat16 l1 = __float2bfloat16(o.y - __bfloat162float(h1));
    __nv_bfloat16 l2 = __float2bfloat16(o.z - __bfloat162float(h2));
    __nv_bfloat16 l3 = __float2bfloat16(o.w - __bfloat162float(h3));
    __nv_bfloat162 ha; ha.x = h0; ha.y = h1;
    __nv_bfloat162 hb; hb.x = h2; hb.y = h3;
    __nv_bfloat162 la; la.x = l0; la.y = l1;
    __nv_bfloat162 lb; lb.x = l2; lb.y = l3;
    *(__nv_bfloat162*)&hi[base]     = ha;
    *(__nv_bfloat162*)&hi[base + 2] = hb;
    *(__nv_bfloat162*)&lo[base]     = la;
    *(__nv_bfloat162*)&lo[base + 2] = lb;
}

__global__ void split_kernel(const float* __restrict__ x,
                             __nv_bfloat16* __restrict__ hi, __nv_bfloat16* __restrict__ lo) {
    size_t i0 = ((size_t)blockIdx.x * blockDim.x + threadIdx.x) * 16;
    #pragma unroll
    for (int u = 0; u < 4; u++) {
        float4 v = *(const float4*)&x[i0 + u * 4];
        split4(v, hi, lo, i0 + u * 4);
    }
}

// ---------------- lambda scalar ----------------
__global__ void lam_kernel(const float* __restrict__ lq1, const float* __restrict__ lk1,
                           const float* __restrict__ lq2, const float* __restrict__ lk2) {
    int l = threadIdx.x;
    float s1 = lq1[l]*lk1[l] + lq1[l+32]*lk1[l+32];
    float s2 = lq2[l]*lk2[l] + lq2[l+32]*lk2[l+32];
    s1 = warp_sum(s1);
    s2 = warp_sum(s2);
    if (l == 0) g_lam = expf(s1) - expf(s2) + LAMBDA_INIT;
}

// ---------------- downsample + split: xd = 0.5*(x[8i+3] + x[8i+4]) ----------------
__global__ void downsample_kernel(const float* __restrict__ x) {
    int idx = blockIdx.x * blockDim.x + threadIdx.x;         // < 2048*256
    int c  = (idx & 255) * 4;
    int m  = idx >> 8;                                       // 0..2047
    int b  = m >> 9, i = m & 511;
    size_t src = ((size_t)b * L_ + 8 * i + 3) * C_ + c;
    float4 a  = *(const float4*)&x[src];
    float4 bb = *(const float4*)&x[src + C_];
    float4 o = { 0.5f*(a.x+bb.x), 0.5f*(a.y+bb.y), 0.5f*(a.z+bb.z), 0.5f*(a.w+bb.w) };
    split4(o, g_xdh, g_xdl, (size_t)m * C_ + c);
}

// ---------------- HMMA split-bf16 GEMM ----------------
// C[m,n] = sum_k A[m,k]*B[n,k], fp32 accum, 3 MMAs: Ah*Bh + Ah*Bl + Al*Bh.
// Block tile 128x128, 8 warps (warp tile 32x64), K-chunk 64, double-buffered cp.async.
// grid.x = 8 * numWeights: blockIdx.x>>3 selects the weight / output.
#define BK_      64
#define TSTRIDE  144                   // bytes per SMEM row (128 data + 16 pad)
#define TSIZE    (128 * TSTRIDE)       // 18432 per tensor
#define GSTAGE   (4 * TSIZE)           // Ah, Al, Bh, Bl
#define GSM_TOTAL (2 * GSTAGE)         // 147456

template<bool SILU>
__global__ __launch_bounds__(256, 1) void gemm_tc(
    const __nv_bfloat16* __restrict__ Ah, const __nv_bfloat16* __restrict__ Al,
    const __nv_bfloat16* __restrict__ BhBase, const __nv_bfloat16* __restrict__ BlBase,
    float* o0, float* o1, float* o2)
{
    extern __shared__ char smc[];
    const uint32_t sb = smem_u32(smc);
    const int t = threadIdx.x, w = t >> 5, lane = t & 31;
    const int wm = w & 3, wn = w >> 2;
    const int which = blockIdx.x >> 3;
    const int m0 = blockIdx.y * 128, n0 = (blockIdx.x & 7) * 128;
    float* Cout = (which == 0) ? o0 : ((which == 1) ? o1 : o2);
    const __nv_bfloat16* Bh = BhBase + (size_t)which * C_ * C_;
    const __nv_bfloat16* Bl = BlBase + (size_t)which * C_ * C_;

    const __nv_bfloat16* srcs[4] = { Ah, Al, Bh, Bl };

    float acc[2][8][4];
    #pragma unroll
    for (int i = 0; i < 2; i++)
        #pragma unroll
        for (int j = 0; j < 8; j++)
            #pragma unroll
            for (int q = 0; q < 4; q++) acc[i][j][q] = 0.f;

    const int ld_rowA = wm*32 + (lane & 15);
    const int ld_kA   = ((lane >> 4) & 1) * 16;
    const int ld_rowB = wn*64 + (lane & 7) + ((lane >> 4) & 1) * 8;
    const int ld_kB   = ((lane >> 3) & 1) * 16;

    #define ISSUE_LOAD(cidx) do { \
        const int _s = (cidx) & 1; \
        const int _k0 = (cidx) * BK_; \
        const uint32_t _sbase = sb + _s * GSTAGE; \
        _Pragma("unroll") \
        for (int u = 0; u < 16; u++) { \
            int idx = u * 256 + t; \
            int tensor = idx >> 10; \
            int rem = idx & 1023; \
            int row = rem >> 3, cc = rem & 7; \
            int rbase = (tensor < 2) ? m0 : n0; \
            const __nv_bfloat16* g = srcs[tensor] + (size_t)(rbase + row) * C_ + _k0 + cc * 8; \
            cp_async16(_sbase + tensor * TSIZE + row * TSTRIDE + cc * 16, g); \
        } \
        asm volatile("cp.async.commit_group;" ::: "memory"); \
    } while (0)

    ISSUE_LOAD(0);

    for (int c = 0; c < 16; c++) {
        if (c + 1 < 16) {
            ISSUE_LOAD(c + 1);
            asm volatile("cp.async.wait_group 1;" ::: "memory");
        } else {
            asm volatile("cp.async.wait_group 0;" ::: "memory");
        }
        __syncthreads();

        const uint32_t sbase = sb + (c & 1) * GSTAGE;
        #pragma unroll
        for (int ks = 0; ks < 4; ks++) {
            uint32_t ah[2][4], al[2][4];
            #pragma unroll
            for (int mf = 0; mf < 2; mf++) {
                uint32_t addr = sbase + (ld_rowA + mf*16) * TSTRIDE + ks*32 + ld_kA;
                ldm_x4(ah[mf], addr);
                ldm_x4(al[mf], addr + TSIZE);
            }
            uint32_t bh[8][2], bl[8][2];
            #pragma unroll
            for (int np = 0; np < 4; np++) {
                uint32_t addr = sbase + 2*TSIZE + (ld_rowB + np*16) * TSTRIDE + ks*32 + ld_kB;
                uint32_t r[4];
                ldm_x4(r, addr);
                bh[np*2][0] = r[0]; bh[np*2][1] = r[1];
                bh[np*2+1][0] = r[2]; bh[np*2+1][1] = r[3];
                ldm_x4(r, addr + TSIZE);
                bl[np*2][0] = r[0]; bl[np*2][1] = r[1];
                bl[np*2+1][0] = r[2]; bl[np*2+1][1] = r[3];
            }
            #pragma unroll
            for (int mf = 0; mf < 2; mf++)
                #pragma unroll
                for (int nf = 0; nf < 8; nf++) {
                    mma_bf16(acc[mf][nf], ah[mf], bh[nf]);
                    mma_bf16(acc[mf][nf], ah[mf], bl[nf]);
                    mma_bf16(acc[mf][nf], al[mf], bh[nf]);
                }
        }
        __syncthreads();
    }

    #pragma unroll
    for (int mf = 0; mf < 2; mf++) {
        int row = m0 + wm*32 + mf*16 + (lane >> 2);
        #pragma unroll
        for (int nf = 0; nf < 8; nf++) {
            int col = n0 + wn*64 + nf*8 + (lane & 3)*2;
            float2 v0 = { acc[mf][nf][0], acc[mf][nf][1] };
            float2 v1 = { acc[mf][nf][2], acc[mf][nf][3] };
            if (SILU) {
                v0.x = v0.x / (1.f + expf(-v0.x));
                v0.y = v0.y / (1.f + expf(-v0.y));
                v1.x = v1.x / (1.f + expf(-v1.x));
                v1.y = v1.y / (1.f + expf(-v1.y));
            }
            *(float2*)&Cout[(size_t)row * C_ + col]       = v0;
            *(float2*)&Cout[(size_t)(row + 8) * C_ + col] = v1;
        }
    }
    #undef ISSUE_LOAD
}

// ---------------- rmsnorm(d=64) + RoPE (pos = head index!) -> bf16 hi/lo ----------
// q additionally pre-scaled by 0.125 (attention logit scale).
__global__ void normrope_kernel(const float* __restrict__ qn_w, const float* __restrict__ kn_w) {
    int gw   = blockIdx.x * (blockDim.x >> 5) + (threadIdx.x >> 5);   // 0..65535
    int lane = threadIdx.x & 31;
    int j  = gw & 1;
    int h  = (gw >> 1) & 7;
    int i  = (gw >> 4) & 511;
    int b  = (gw >> 13) & 3;
    int qk = (gw >> 15) & 1;

    const float* src = (qk ? g_k : g_q) + ((size_t)(b * R_ + i) * C_ + h * 128 + j * 64);
    const float* wv  = qk ? kn_w : qn_w;

    float x1 = src[lane], x2 = src[lane + 32];
    float ss = warp_sum(x1*x1 + x2*x2);
    float inv = 1.0f / sqrtf(ss * (1.0f / 64.0f) + EPS_);
    float n1 = x1 * inv * wv[lane];
    float n2 = x2 * inv * wv[lane + 32];

    float freq = expf(-(float)lane * (9.210340371976184f / 32.0f));
    float s, c;
    sincosf((float)h * freq, &s, &c);

    float v1 = n1 * c - n2 * s;
    float v2 = n1 * s + n2 * c;
    if (!qk) { v1 *= 0.125f; v2 *= 0.125f; }

    __nv_bfloat16* dh_ = qk ? (j ? g_k2h : g_k1h) : (j ? g_q2h : g_q1h);
    __nv_bfloat16* dl_ = qk ? (j ? g_k2l : g_k1l) : (j ? g_q2l : g_q1l);
    size_t base = (size_t)((b * H_ + h) * R_ + i) * D_;
    __nv_bfloat16 h1 = __float2bfloat16(v1), h2 = __float2bfloat16(v2);
    dh_[base + lane]      = h1;
    dh_[base + lane + 32] = h2;
    dl_[base + lane]      = __float2bfloat16(v1 - __bfloat162float(h1));
    dl_[base + lane + 32] = __float2bfloat16(v2 - __bfloat162float(h2));
}

// ---------------- V transpose + split: g_v[b,key,h*128+dim] -> Vt[bh][dim][key] ----
#define VT_SM (128 * 132 * 4)
__global__ void vtrans_kernel() {
    extern __shared__ float smv[];          // [128 keys][132]
    const int kt = blockIdx.x, h = blockIdx.y, b = blockIdx.z;
    const int bh = b * H_ + h;
    const int t = threadIdx.x;              // 256

    #pragma unroll
    for (int u = 0; u < 16; u++) {
        int idx = u * 256 + t;              // 0..4095 float4 chunks
        int key = idx >> 5, c4 = (idx & 31) * 4;
        float4 v = *(const float4*)&g_v[((size_t)(b * R_ + kt * 128 + key)) * C_ + h * 128 + c4];
        *(float4*)&smv[key * 132 + c4] = v;
    }
    __syncthreads();

    int dim = t >> 1, k0 = (t & 1) * 64;
    size_t ob = ((size_t)bh * 128 + dim) * R_ + kt * 128 + k0;
    #pragma unroll
    for (int i = 0; i < 64; i += 2) {
        float e0 = smv[(k0 + i) * 132 + dim];
        float e1 = smv[(k0 + i + 1) * 132 + dim];
        __nv_bfloat16 h0 = __float2bfloat16(e0), h1 = __float2bfloat16(e1);
        __nv_bfloat162 hp; hp.x = h0; hp.y = h1;
        __nv_bfloat162 lp;
        lp.x = __float2bfloat16(e0 - __bfloat162float(h0));
        lp.y = __float2bfloat16(e1 - __bfloat162float(h1));
        *(__nv_bfloat162*)&g_vth[ob + i] = hp;
        *(__nv_bfloat162*)&g_vtl[ob + i] = lp;
    }
}

// ---------------- tensor-core differential flash attention + fused headnorm -------
// grid (4, H, B), 256 threads (8 warps x 16 q-rows). Online softmax per tensor.
#define ASTR  144
#define QOFF  0
#define KOFF  (4 * 128 * ASTR)              // 73728
#define VSTR  272
#define VTSZ  (128 * VSTR)                  // 34816
#define VOFF_ (KOFF + 4 * 128 * ASTR)       // 147456
#define ASM_TOTAL (VOFF_ + 2 * VTSZ)        // 217088

__global__ __launch_bounds__(256, 1) void attn_tc(const float* __restrict__ hw) {
    extern __shared__ char smc[];
    const uint32_t sb = smem_u32(smc);
    const int t = threadIdx.x, w = t >> 5, lane = t & 31;
    const int b = blockIdx.z, h = blockIdx.y, bh = b * H_ + h;
    const int q0 = blockIdx.x * 128;

    // ---- Q tiles (once) ----
    {
        const __nv_bfloat16* qsrc[4] = { g_q1h, g_q1l, g_q2h, g_q2l };
        #pragma unroll
        for (int u = 0; u < 16; u++) {
            int idx = u * 256 + t;
            int tensor = idx >> 10, rem = idx & 1023;
            int row = rem >> 3, cc = rem & 7;
            const __nv_bfloat16* g = qsrc[tensor] + ((size_t)bh * R_ + q0 + row) * D_ + cc * 8;
            cp_async16(sb + QOFF + tensor * (128*ASTR) + row * ASTR + cc * 16, g);
        }
    }
    asm volatile("cp.async.commit_group;" ::: "memory");

    float Oc[2][16][4];
    #pragma unroll
    for (int tt = 0; tt < 2; tt++)
        #pragma unroll
        for (int nf = 0; nf < 16; nf++)
            #pragma unroll
            for (int q = 0; q < 4; q++) Oc[tt][nf][q] = 0.f;
    float mA[2] = { -1e30f, -1e30f }, mB[2] = { -1e30f, -1e30f };
    float sA[2] = { 0.f, 0.f },       sB[2] = { 0.f, 0.f };

    const uint32_t aq_base = sb + QOFF + (w*16 + (lane & 15)) * ASTR + ((lane >> 4) & 1) * 16;
    const uint32_t kb_base = sb + KOFF + ((lane & 7) + ((lane >> 4) & 1) * 8) * ASTR + ((lane >> 3) & 1) * 16;
    const uint32_t vb_base = sb + VOFF_ + ((lane & 7) + ((lane >> 4) & 1) * 8) * VSTR + ((lane >> 3) & 1) * 16;

    #pragma unroll 1
    for (int kt = 0; kt < 4; kt++) {
        __syncthreads();   // previous compute done before overwrite
        {
            const __nv_bfloat16* ksrc[4] = { g_k1h, g_k1l, g_k2h, g_k2l };
            #pragma unroll
            for (int u = 0; u < 16; u++) {
                int idx = u * 256 + t;
                int tensor = idx >> 10, rem = idx & 1023;
                int row = rem >> 3, cc = rem & 7;
                const __nv_bfloat16* g = ksrc[tensor] + ((size_t)bh * R_ + kt * 128 + row) * D_ + cc * 8;
                cp_async16(sb + KOFF + tensor * (128*ASTR) + row * ASTR + cc * 16, g);
            }
            #pragma unroll
            for (int u = 0; u < 16; u++) {
                int idx = u * 256 + t;
                int half = idx >> 11, rem = idx & 2047;
                int row = rem >> 4, cc = rem & 15;
                const __nv_bfloat16* g = (half ? g_vtl : g_vth)
                                       + ((size_t)bh * 128 + row) * R_ + kt * 128 + cc * 8;
                cp_async16(sb + VOFF_ + half * VTSZ + row * VSTR + cc * 16, g);
            }
        }
        asm volatile("cp.async.commit_group;" ::: "memory");
        asm volatile("cp.async.wait_group 0;" ::: "memory");
        __syncthreads();

        #pragma unroll
        for (int tt = 0; tt < 2; tt++) {
            // ---- S = Qtt @ Ktt^T (split 3-MMA) ----
            float S[16][4];
            #pragma unroll
            for (int nf = 0; nf < 16; nf++)
                #pragma unroll
                for (int q = 0; q < 4; q++) S[nf][q] = 0.f;

            #pragma unroll
            for (int kk = 0; kk < 4; kk++) {
                uint32_t ah[4], al[4];
                ldm_x4(ah, aq_base + (tt*2+0) * (128*ASTR) + kk*32);
                ldm_x4(al, aq_base + (tt*2+1) * (128*ASTR) + kk*32);
                #pragma unroll
                for (int np = 0; np < 8; np++) {
                    uint32_t bh4[4], bl4[4];
                    uint32_t ka = kb_base + (tt*2) * (128*ASTR) + np * 16 * ASTR + kk*32;
                    ldm_x4(bh4, ka);
                    ldm_x4(bl4, ka + 128*ASTR);
                    mma_bf16(S[2*np],   ah, bh4);
                    mma_bf16(S[2*np],   ah, bl4);
                    mma_bf16(S[2*np],   al, bh4);
                    mma_bf16(S[2*np+1], ah, bh4+2);
                    mma_bf16(S[2*np+1], ah, bl4+2);
                    mma_bf16(S[2*np+1], al, bh4+2);
                }
            }

            // ---- online softmax update ----
            float mla = -1e30f, mlb = -1e30f;
            #pragma unroll
            for (int nf = 0; nf < 16; nf++) {
                mla = fmaxf(mla, fmaxf(S[nf][0], S[nf][1]));
                mlb = fmaxf(mlb, fmaxf(S[nf][2], S[nf][3]));
            }
            mla = fmaxf(mla, __shfl_xor_sync(0xffffffffu, mla, 1));
            mla = fmaxf(mla, __shfl_xor_sync(0xffffffffu, mla, 2));
            mlb = fmaxf(mlb, __shfl_xor_sync(0xffffffffu, mlb, 1));
            mlb = fmaxf(mlb, __shfl_xor_sync(0xffffffffu, mlb, 2));
            float mna = fmaxf(mA[tt], mla), mnb = fmaxf(mB[tt], mlb);
            float fa = __expf(mA[tt] - mna), fb = __expf(mB[tt] - mnb);
            mA[tt] = mna; mB[tt] = mnb;
            float ra = 0.f, rb = 0.f;
            #pragma unroll
            for (int nf = 0; nf < 16; nf++) {
                S[nf][0] = __expf(S[nf][0] - mna);
                S[nf][1] = __expf(S[nf][1] - mna);
                S[nf][2] = __expf(S[nf][2] - mnb);
                S[nf][3] = __expf(S[nf][3] - mnb);
                ra += S[nf][0] + S[nf][1];
                rb += S[nf][2] + S[nf][3];
                Oc[tt][nf][0] *= fa; Oc[tt][nf][1] *= fa;
                Oc[tt][nf][2] *= fb; Oc[tt][nf][3] *= fb;
            }
            sA[tt] = sA[tt] * fa + ra;
            sB[tt] = sB[tt] * fb + rb;

            // ---- O += P @ V (split 3-MMA, P frags built in-register) ----
            #pragma unroll
            for (int kf = 0; kf < 8; kf++) {
                uint32_t pah[4], pal[4];
                #pragma unroll
                for (int half = 0; half < 2; half++) {
                    const float* sv = S[2*kf + half];
                    __nv_bfloat16 e0 = __float2bfloat16(sv[0]);
                    __nv_bfloat16 e1 = __float2bfloat16(sv[1]);
                    __nv_bfloat16 e2 = __float2bfloat16(sv[2]);
                    __nv_bfloat16 e3 = __float2bfloat16(sv[3]);
                    pah[half*2]   = pack_bf16x2(__bfloat162float(e0), __bfloat162float(e1));
                    pah[half*2+1] = pack_bf16x2(__bfloat162float(e2), __bfloat162float(e3));
                    pal[half*2]   = pack_bf16x2(sv[0] - __bfloat162float(e0),
                                                sv[1] - __bfloat162float(e1));
                    pal[half*2+1] = pack_bf16x2(sv[2] - __bfloat162float(e2),
                                                sv[3] - __bfloat162float(e3));
                }
                #pragma unroll
                for (int np = 0; np < 8; np++) {
                    uint32_t vh4[4], vl4[4];
                    uint32_t va = vb_base + np * 16 * VSTR + kf*32;
                    ldm_x4(vh4, va);
                    ldm_x4(vl4, va + VTSZ);
                    mma_bf16(Oc[tt][2*np],   pah, vh4);
                    mma_bf16(Oc[tt][2*np],   pah, vl4);
                    mma_bf16(Oc[tt][2*np],   pal, vh4);
                    mma_bf16(Oc[tt][2*np+1], pah, vh4+2);
                    mma_bf16(Oc[tt][2*np+1], pah, vl4+2);
                    mma_bf16(Oc[tt][2*np+1], pal, vh4+2);
                }
            }
        }
    }

    // ---- epilogue: combine, fused head rmsnorm * 0.2, bf16 hi/lo split ----
    #pragma unroll
    for (int tt = 0; tt < 2; tt++) {
        sA[tt] += __shfl_xor_sync(0xffffffffu, sA[tt], 1);
        sA[tt] += __shfl_xor_sync(0xffffffffu, sA[tt], 2);
        sB[tt] += __shfl_xor_sync(0xffffffffu, sB[tt], 1);
        sB[tt] += __shfl_xor_sync(0xffffffffu, sB[tt], 2);
    }
    float lam = g_lam;
    float i1a = 1.f / sA[0], i1b = 1.f / sB[0];
    float i2a = lam / sA[1], i2b = lam / sB[1];

    float Dv[16][4];
    float ssa = 0.f, ssb = 0.f;
    #pragma unroll
    for (int nf = 0; nf < 16; nf++) {
        Dv[nf][0] = Oc[0][nf][0] * i1a - Oc[1][nf][0] * i2a;
        Dv[nf][1] = Oc[0][nf][1] * i1a - Oc[1][nf][1] * i2a;
        Dv[nf][2] = Oc[0][nf][2] * i1b - Oc[1][nf][2] * i2b;
        Dv[nf][3] = Oc[0][nf][3] * i1b - Oc[1][nf][3] * i2b;
        ssa += Dv[nf][0]*Dv[nf][0] + Dv[nf][1]*Dv[nf][1];
        ssb += Dv[nf][2]*Dv[nf][2] + Dv[nf][3]*Dv[nf][3];
    }
    ssa += __shfl_xor_sync(0xffffffffu, ssa, 1);
    ssa += __shfl_xor_sync(0xffffffffu, ssa, 2);
    ssb += __shfl_xor_sync(0xffffffffu, ssb, 1);
    ssb += __shfl_xor_sync(0xffffffffu, ssb, 2);
    float na = 0.2f / sqrtf(ssa * (1.0f / 128.0f) + EPS_);
    float nb = 0.2f / sqrtf(ssb * (1.0f / 128.0f) + EPS_);

    int rowa = b * R_ + q0 + w * 16 + (lane >> 2);
    int colb = h * 128 + 2 * (lane & 3);
    #pragma unroll
    for (int nf = 0; nf < 16; nf++) {
        int col = colb + 8 * nf;
        float2 wv = *(const float2*)&hw[col - h * 128];
        float d0 = Dv[nf][0] * na * wv.x, d1 = Dv[nf][1] * na * wv.y;
        float d2 = Dv[nf][2] * nb * wv.x, d3 = Dv[nf][3] * nb * wv.y;
        __nv_bfloat16 h0 = __float2bfloat16(d0), h1 = __float2bfloat16(d1);
        __nv_bfloat16 h2 = __float2bfloat16(d2), h3 = __float2bfloat16(d3);
        __nv_bfloat162 hp0; hp0.x = h0; hp0.y = h1;
        __nv_bfloat162 hp1; hp1.x = h2; hp1.y = h3;
        __nv_bfloat162 lp0, lp1;
        lp0.x = __float2bfloat16(d0 - __bfloat162float(h0));
        lp0.y = __float2bfloat16(d1 - __bfloat162float(h1));
        lp1.x = __float2bfloat16(d2 - __bfloat162float(h2));
        lp1.y = __float2bfloat16(d3 - __bfloat162float(h3));
        *(__nv_bfloat162*)&g_dh[(size_t)rowa * C_ + col]       = hp0;
        *(__nv_bfloat162*)&g_dl[(size_t)rowa * C_ + col]       = lp0;
        *(__nv_bfloat162*)&g_dh[(size_t)(rowa + 8) * C_ + col] = hp1;
        *(__nv_bfloat162*)&g_dl[(size_t)(rowa + 8) * C_ + col] = lp1;
    }
}

// ---------------- upsample 512 -> 4096 ----------------
__global__ void upsample_kernel(float* __restrict__ out, const float* __restrict__ low) {
    int idx = blockIdx.x * blockDim.x + threadIdx.x;     // < 4194304
    int c = (idx & 255) * 4;
    int t = idx >> 8;                                    // 0..16383
    int j = t & 4095, b = t >> 12;
    float coord = fminf(fmaxf(0.125f * (float)j - 0.4375f, 0.0f), 511.0f);
    int lo = (int)coord;
    int hi = min(lo + 1, 511);
    float wgt = coord - (float)lo;
    const float* lb = low + (size_t)b * R_ * C_;
    float4 a  = *(const float4*)&lb[(size_t)lo * C_ + c];
    float4 bb = *(const float4*)&lb[(size_t)hi * C_ + c];
    float4 o = { a.x*(1.f-wgt) + bb.x*wgt, a.y*(1.f-wgt) + bb.y*wgt,
                 a.z*(1.f-wgt) + bb.z*wgt, a.w*(1.f-wgt) + bb.w*wgt };
    *(float4*)&out[(size_t)(b * L_ + j) * C_ + c] = o;
}

// ---------------- launch ----------------
extern "C" void kernel_launch(void* const* d_in, const int* in_sizes, int n_in,
                              void* d_out, int out_size) {
    (void)in_sizes; (void)n_in; (void)out_size;
    const float* x   = (const float*)d_in[0];
    const float* W[4] = { (const float*)d_in[1], (const float*)d_in[2],
                          (const float*)d_in[3], (const float*)d_in[4] };  // Wq,Wk,Wv,Wo
    const float* qn  = (const float*)d_in[5];
    const float* kn  = (const float*)d_in[6];
    const float* hw  = (const float*)d_in[7];
    const float* lq1 = (const float*)d_in[8];
    const float* lk1 = (const float*)d_in[9];
    const float* lq2 = (const float*)d_in[10];
    const float* lk2 = (const float*)d_in[11];

    float* out     = (float*)d_out;
    float* out_low = out + FULL_ELEMS;

    float *p_q, *p_k, *p_v;
    cudaGetSymbolAddress((void**)&p_q, g_q);
    cudaGetSymbolAddress((void**)&p_k, g_k);
    cudaGetSymbolAddress((void**)&p_v, g_v);
    __nv_bfloat16 *p_xdh, *p_xdl, *p_dh, *p_dl, *p_wh, *p_wl;
    cudaGetSymbolAddress((void**)&p_xdh, g_xdh);
    cudaGetSymbolAddress((void**)&p_xdl, g_xdl);
    cudaGetSymbolAddress((void**)&p_dh,  g_dh);
    cudaGetSymbolAddress((void**)&p_dl,  g_dl);
    cudaGetSymbolAddress((void**)&p_wh,  g_wh);
    cudaGetSymbolAddress((void**)&p_wl,  g_wl);

    static int attr_done = 0;
    if (!attr_done) {
        cudaFuncSetAttribute(gemm_tc<false>, cudaFuncAttributeMaxDynamicSharedMemorySize, GSM_TOTAL);
        cudaFuncSetAttribute(gemm_tc<true>,  cudaFuncAttributeMaxDynamicSharedMemorySize, GSM_TOTAL);
        cudaFuncSetAttribute(attn_tc,        cudaFuncAttributeMaxDynamicSharedMemorySize, ASM_TOTAL);
        cudaFuncSetAttribute(vtrans_kernel,  cudaFuncAttributeMaxDynamicSharedMemorySize, VT_SM);
        attr_done = 1;
    }

    lam_kernel<<<1, 32>>>(lq1, lk1, lq2, lk2);
    downsample_kernel<<<2048, 256>>>(x);
    for (int i = 0; i < 4; i++)
        split_kernel<<<256, 256>>>(W[i], p_wh + (size_t)i * C_ * C_, p_wl + (size_t)i * C_ * C_);

    // fused QKV GEMM: grid.x = 3 weights * 8 n-tiles
    gemm_tc<false><<<dim3(24, 16), 256, GSM_TOTAL>>>(p_xdh, p_xdl, p_wh, p_wl, p_q, p_k, p_v);

    normrope_kernel<<<16384, 128>>>(qn, kn);
    vtrans_kernel<<<dim3(4, 8, 4), 256, VT_SM>>>();
    attn_tc<<<dim3(4, 8, 4), 256, ASM_TOTAL>>>(hw);

    // Wo GEMM + SiLU (which==0 -> out_low)
    gemm_tc<true><<<dim3(8, 16), 256, GSM_TOTAL>>>(p_dh, p_dl,
        p_wh + 3*(size_t)C_*C_, p_wl + 3*(size_t)C_*C_, out_low, out_low, out_low);

    upsample_kernel<<<16384, 256>>>(out, out_low);
}

// round 14
// speedup vs baseline: 1.6217x; 1.0029x over previous
#include <cuda_runtime.h>
#include <cuda_bf16.h>
#include <math.h>
#include <stdint.h>

// ---------------- problem constants ----------------
#define B_  4
#define L_  4096
#define C_  1024
#define H_  8
#define D_  64      // C / (2H)
#define R_  512     // int(L^0.75)
#define M_  (B_*R_) // 2048 GEMM rows
#define FULL_ELEMS (B_*L_*C_)   // 16777216
#define LAMBDA_INIT 0.8f
#define EPS_ 1e-6f

// ---------------- device scratch (no allocs allowed) ----------------
__device__ float g_q   [M_*C_];
__device__ float g_k   [M_*C_];
__device__ float g_v   [M_*C_];
__device__ float g_lam;

// bf16 hi/lo split operands for tensor-core GEMMs
__device__ __nv_bfloat16 g_xdh[M_*C_], g_xdl[M_*C_];       // downsampled x
__device__ __nv_bfloat16 g_dh [M_*C_], g_dl [M_*C_];       // head-normed diff
__device__ __nv_bfloat16 g_wh [4][C_*C_], g_wl[4][C_*C_];  // Wq,Wk,Wv,Wo

// bf16 hi/lo Q/K (normrope output, q pre-scaled by 0.125) [B*H][R][D]
__device__ __nv_bfloat16 g_q1h[B_*H_*R_*D_], g_q1l[B_*H_*R_*D_];
__device__ __nv_bfloat16 g_q2h[B_*H_*R_*D_], g_q2l[B_*H_*R_*D_];
__device__ __nv_bfloat16 g_k1h[B_*H_*R_*D_], g_k1l[B_*H_*R_*D_];
__device__ __nv_bfloat16 g_k2h[B_*H_*R_*D_], g_k2l[B_*H_*R_*D_];
// transposed V hi/lo: [B*H][dim 128][key 512]
__device__ __nv_bfloat16 g_vth[B_*H_*128*R_], g_vtl[B_*H_*128*R_];

// ---------------- warp helpers ----------------
__device__ __forceinline__ float warp_sum(float v) {
    #pragma unroll
    for (int o = 16; o > 0; o >>= 1) v += __shfl_xor_sync(0xffffffffu, v, o);
    return v;
}

// ---------------- PTX helpers (HMMA path: valid on compute_103 PTX target) ----
__device__ __forceinline__ uint32_t smem_u32(const void* p) {
    uint32_t a;
    asm("{ .reg .u64 t; cvta.to.shared.u64 t, %1; cvt.u32.u64 %0, t; }" : "=r"(a) : "l"(p));
    return a;
}
__device__ __forceinline__ void cp_async16(uint32_t dst, const void* src) {
    asm volatile("cp.async.cg.shared.global [%0], [%1], 16;" :: "r"(dst), "l"(src) : "memory");
}
__device__ __forceinline__ void ldm_x4(uint32_t* r, uint32_t addr) {
    asm volatile("ldmatrix.sync.aligned.m8n8.x4.shared.b16 {%0,%1,%2,%3}, [%4];"
                 : "=r"(r[0]), "=r"(r[1]), "=r"(r[2]), "=r"(r[3]) : "r"(addr));
}
__device__ __forceinline__ void mma_bf16(float* c, const uint32_t* a, const uint32_t* b) {
    asm volatile(
        "mma.sync.aligned.m16n8k16.row.col.f32.bf16.bf16.f32 "
        "{%0,%1,%2,%3}, {%4,%5,%6,%7}, {%8,%9}, {%0,%1,%2,%3};"
        : "+f"(c[0]), "+f"(c[1]), "+f"(c[2]), "+f"(c[3])
        : "r"(a[0]), "r"(a[1]), "r"(a[2]), "r"(a[3]), "r"(b[0]), "r"(b[1]));
}
// pack two floats into bf16x2: low half = lo, high half = hi
__device__ __forceinline__ uint32_t pack_bf16x2(float lo, float hi) {
    uint32_t r;
    asm("cvt.rn.bf16x2.f32 %0, %1, %2;" : "=r"(r) : "f"(hi), "f"(lo));
    return r;
}

// ---------------- fp32 -> (bf16 hi, bf16 lo) split ----------------
__device__ __forceinline__ void split4(float4 o, __nv_bfloat16* hi, __nv_bfloat16* lo, size_t base) {
    __nv_bfloat16 h0 = __float2bfloat16(o.x), h1 = __float2bfloat16(o.y);
    __nv_bfloat16 h2 = __float2bfloat16(o.z), h3 = __float2bfloat16(o.w);
    __nv_bfloat16 l0 = __float2bfloat16(o.x - __bfloat162float(h0));
    __nv_bfloat16 l1 = __float2bfloat16(o.y - __bfloat162float(h1));
    __nv_bfloat16 l2 = __float2bfloat16(o.z - __bfloat162float(h2));
    __nv_bfloat16 l3 = __float2bfloat16(o.w - __bfloat162float(h3));
    __nv_bfloat162 ha; ha.x = h0; ha.y = h1;
    __nv_bfloat162 hb; hb.x = h2; hb.y = h3;
    __nv_bfloat162 la; la.x = l0; la.y = l1;
    __nv_bfloat162 lb; lb.x = l2; lb.y = l3;
    *(__nv_bfloat162*)&hi[base]     = ha;
    *(__nv_bfloat162*)&hi[base + 2] = hb;
    *(__nv_bfloat162*)&lo[base]     = la;
    *(__nv_bfloat162*)&lo[base + 2] = lb;
}

__global__ void split_kernel(const float* __restrict__ x,
                             __nv_bfloat16* __restrict__ hi, __nv_bfloat16* __restrict__ lo) {
    size_t i0 = ((size_t)blockIdx.x * blockDim.x + threadIdx.x) * 16;
    #pragma unroll
    for (int u = 0; u < 4; u++) {
        float4 v = *(const float4*)&x[i0 + u * 4];
        split4(v, hi, lo, i0 + u * 4);
    }
}

// ---------------- lambda scalar ----------------
__global__ void lam_kernel(const float* __restrict__ lq1, const float* __restrict__ lk1,
                           const float* __restrict__ lq2, const float* __restrict__ lk2) {
    int l = threadIdx.x;
    float s1 = lq1[l]*lk1[l] + lq1[l+32]*lk1[l+32];
    float s2 = lq2[l]*lk2[l] + lq2[l+32]*lk2[l+32];
    s1 = warp_sum(s1);
    s2 = warp_sum(s2);
    if (l == 0) g_lam = expf(s1) - expf(s2) + LAMBDA_INIT;
}

// ---------------- downsample + split: xd = 0.5*(x[8i+3] + x[8i+4]) ----------------
__global__ void downsample_kernel(const float* __restrict__ x) {
    int idx = blockIdx.x * blockDim.x + threadIdx.x;         // < 2048*256
    int c  = (idx & 255) * 4;
    int m  = idx >> 8;                                       // 0..2047
    int b  = m >> 9, i = m & 511;
    size_t src = ((size_t)b * L_ + 8 * i + 3) * C_ + c;
    float4 a  = *(const float4*)&x[src];
    float4 bb = *(const float4*)&x[src + C_];
    float4 o = { 0.5f*(a.x+bb.x), 0.5f*(a.y+bb.y), 0.5f*(a.z+bb.z), 0.5f*(a.w+bb.w) };
    split4(o, g_xdh, g_xdl, (size_t)m * C_ + c);
}

// ---------------- HMMA split-bf16 GEMM ----------------
// C[m,n] = sum_k A[m,k]*B[n,k], fp32 accum, 3 MMAs: Ah*Bh + Ah*Bl + Al*Bh.
// Block tile 128x128, 8 warps (warp tile 32x64), K-chunk 64, double-buffered cp.async.
// grid.x = 8 * numWeights: blockIdx.x>>3 selects the weight / output.
#define BK_      64
#define TSTRIDE  144                   // bytes per SMEM row (128 data + 16 pad)
#define TSIZE    (128 * TSTRIDE)       // 18432 per tensor
#define GSTAGE   (4 * TSIZE)           // Ah, Al, Bh, Bl
#define GSM_TOTAL (2 * GSTAGE)         // 147456

template<bool SILU>
__global__ __launch_bounds__(256, 1) void gemm_tc(
    const __nv_bfloat16* __restrict__ Ah, const __nv_bfloat16* __restrict__ Al,
    const __nv_bfloat16* __restrict__ BhBase, const __nv_bfloat16* __restrict__ BlBase,
    float* o0, float* o1, float* o2)
{
    extern __shared__ char smc[];
    const uint32_t sb = smem_u32(smc);
    const int t = threadIdx.x, w = t >> 5, lane = t & 31;
    const int wm = w & 3, wn = w >> 2;
    const int which = blockIdx.x >> 3;
    const int m0 = blockIdx.y * 128, n0 = (blockIdx.x & 7) * 128;
    float* Cout = (which == 0) ? o0 : ((which == 1) ? o1 : o2);
    const __nv_bfloat16* Bh = BhBase + (size_t)which * C_ * C_;
    const __nv_bfloat16* Bl = BlBase + (size_t)which * C_ * C_;

    const __nv_bfloat16* srcs[4] = { Ah, Al, Bh, Bl };

    float acc[2][8][4];
    #pragma unroll
    for (int i = 0; i < 2; i++)
        #pragma unroll
        for (int j = 0; j < 8; j++)
            #pragma unroll
            for (int q = 0; q < 4; q++) acc[i][j][q] = 0.f;

    const int ld_rowA = wm*32 + (lane & 15);
    const int ld_kA   = ((lane >> 4) & 1) * 16;
    const int ld_rowB = wn*64 + (lane & 7) + ((lane >> 4) & 1) * 8;
    const int ld_kB   = ((lane >> 3) & 1) * 16;

    #define ISSUE_LOAD(cidx) do { \
        const int _s = (cidx) & 1; \
        const int _k0 = (cidx) * BK_; \
        const uint32_t _sbase = sb + _s * GSTAGE; \
        _Pragma("unroll") \
        for (int u = 0; u < 16; u++) { \
            int idx = u * 256 + t; \
            int tensor = idx >> 10; \
            int rem = idx & 1023; \
            int row = rem >> 3, cc = rem & 7; \
            int rbase = (tensor < 2) ? m0 : n0; \
            const __nv_bfloat16* g = srcs[tensor] + (size_t)(rbase + row) * C_ + _k0 + cc * 8; \
            cp_async16(_sbase + tensor * TSIZE + row * TSTRIDE + cc * 16, g); \
        } \
        asm volatile("cp.async.commit_group;" ::: "memory"); \
    } while (0)

    ISSUE_LOAD(0);

    for (int c = 0; c < 16; c++) {
        if (c + 1 < 16) {
            ISSUE_LOAD(c + 1);
            asm volatile("cp.async.wait_group 1;" ::: "memory");
        } else {
            asm volatile("cp.async.wait_group 0;" ::: "memory");
        }
        __syncthreads();

        const uint32_t sbase = sb + (c & 1) * GSTAGE;
        #pragma unroll
        for (int ks = 0; ks < 4; ks++) {
            uint32_t ah[2][4], al[2][4];
            #pragma unroll
            for (int mf = 0; mf < 2; mf++) {
                uint32_t addr = sbase + (ld_rowA + mf*16) * TSTRIDE + ks*32 + ld_kA;
                ldm_x4(ah[mf], addr);
                ldm_x4(al[mf], addr + TSIZE);
            }
            uint32_t bh[8][2], bl[8][2];
            #pragma unroll
            for (int np = 0; np < 4; np++) {
                uint32_t addr = sbase + 2*TSIZE + (ld_rowB + np*16) * TSTRIDE + ks*32 + ld_kB;
                uint32_t r[4];
                ldm_x4(r, addr);
                bh[np*2][0] = r[0]; bh[np*2][1] = r[1];
                bh[np*2+1][0] = r[2]; bh[np*2+1][1] = r[3];
                ldm_x4(r, addr + TSIZE);
                bl[np*2][0] = r[0]; bl[np*2][1] = r[1];
                bl[np*2+1][0] = r[2]; bl[np*2+1][1] = r[3];
            }
            #pragma unroll
            for (int mf = 0; mf < 2; mf++)
                #pragma unroll
                for (int nf = 0; nf < 8; nf++) {
                    mma_bf16(acc[mf][nf], ah[mf], bh[nf]);
                    mma_bf16(acc[mf][nf], ah[mf], bl[nf]);
                    mma_bf16(acc[mf][nf], al[mf], bh[nf]);
                }
        }
        __syncthreads();
    }

    #pragma unroll
    for (int mf = 0; mf < 2; mf++) {
        int row = m0 + wm*32 + mf*16 + (lane >> 2);
        #pragma unroll
        for (int nf = 0; nf < 8; nf++) {
            int col = n0 + wn*64 + nf*8 + (lane & 3)*2;
            float2 v0 = { acc[mf][nf][0], acc[mf][nf][1] };
            float2 v1 = { acc[mf][nf][2], acc[mf][nf][3] };
            if (SILU) {
                v0.x = v0.x / (1.f + expf(-v0.x));
                v0.y = v0.y / (1.f + expf(-v0.y));
                v1.x = v1.x / (1.f + expf(-v1.x));
                v1.y = v1.y / (1.f + expf(-v1.y));
            }
            *(float2*)&Cout[(size_t)row * C_ + col]       = v0;
            *(float2*)&Cout[(size_t)(row + 8) * C_ + col] = v1;
        }
    }
    #undef ISSUE_LOAD
}

// ---------------- rmsnorm(d=64) + RoPE (pos = head index!) -> bf16 hi/lo ----------
// q additionally pre-scaled by 0.125 (attention logit scale).
__global__ void normrope_kernel(const float* __restrict__ qn_w, const float* __restrict__ kn_w) {
    int gw   = blockIdx.x * (blockDim.x >> 5) + (threadIdx.x >> 5);   // 0..65535
    int lane = threadIdx.x & 31;
    int j  = gw & 1;
    int h  = (gw >> 1) & 7;
    int i  = (gw >> 4) & 511;
    int b  = (gw >> 13) & 3;
    int qk = (gw >> 15) & 1;

    const float* src = (qk ? g_k : g_q) + ((size_t)(b * R_ + i) * C_ + h * 128 + j * 64);
    const float* wv  = qk ? kn_w : qn_w;

    float x1 = src[lane], x2 = src[lane + 32];
    float ss = warp_sum(x1*x1 + x2*x2);
    float inv = 1.0f / sqrtf(ss * (1.0f / 64.0f) + EPS_);
    float n1 = x1 * inv * wv[lane];
    float n2 = x2 * inv * wv[lane + 32];

    float freq = expf(-(float)lane * (9.210340371976184f / 32.0f));
    float s, c;
    sincosf((float)h * freq, &s, &c);

    float v1 = n1 * c - n2 * s;
    float v2 = n1 * s + n2 * c;
    if (!qk) { v1 *= 0.125f; v2 *= 0.125f; }

    __nv_bfloat16* dh_ = qk ? (j ? g_k2h : g_k1h) : (j ? g_q2h : g_q1h);
    __nv_bfloat16* dl_ = qk ? (j ? g_k2l : g_k1l) : (j ? g_q2l : g_q1l);
    size_t base = (size_t)((b * H_ + h) * R_ + i) * D_;
    __nv_bfloat16 h1 = __float2bfloat16(v1), h2 = __float2bfloat16(v2);
    dh_[base + lane]      = h1;
    dh_[base + lane + 32] = h2;
    dl_[base + lane]      = __float2bfloat16(v1 - __bfloat162float(h1));
    dl_[base + lane + 32] = __float2bfloat16(v2 - __bfloat162float(h2));
}

// ---------------- V transpose + split: g_v[b,key,h*128+dim] -> Vt[bh][dim][key] ----
#define VT_SM (128 * 132 * 4)
__global__ void vtrans_kernel() {
    extern __shared__ float smv[];          // [128 keys][132]
    const int kt = blockIdx.x, h = blockIdx.y, b = blockIdx.z;
    const int bh = b * H_ + h;
    const int t = threadIdx.x;              // 256

    #pragma unroll
    for (int u = 0; u < 16; u++) {
        int idx = u * 256 + t;              // 0..4095 float4 chunks
        int key = idx >> 5, c4 = (idx & 31) * 4;
        float4 v = *(const float4*)&g_v[((size_t)(b * R_ + kt * 128 + key)) * C_ + h * 128 + c4];
        *(float4*)&smv[key * 132 + c4] = v;
    }
    __syncthreads();

    int dim = t >> 1, k0 = (t & 1) * 64;
    size_t ob = ((size_t)bh * 128 + dim) * R_ + kt * 128 + k0;
    #pragma unroll
    for (int i = 0; i < 64; i += 2) {
        float e0 = smv[(k0 + i) * 132 + dim];
        float e1 = smv[(k0 + i + 1) * 132 + dim];
        __nv_bfloat16 h0 = __float2bfloat16(e0), h1 = __float2bfloat16(e1);
        __nv_bfloat162 hp; hp.x = h0; hp.y = h1;
        __nv_bfloat162 lp;
        lp.x = __float2bfloat16(e0 - __bfloat162float(h0));
        lp.y = __float2bfloat16(e1 - __bfloat162float(h1));
        *(__nv_bfloat162*)&g_vth[ob + i] = hp;
        *(__nv_bfloat162*)&g_vtl[ob + i] = lp;
    }
}

// ---------------- tensor-core differential flash attention + fused headnorm -------
// grid (4, H, B), 256 threads (8 warps x 16 q-rows). Online softmax per tensor.
#define ASTR  144
#define QOFF  0
#define KOFF  (4 * 128 * ASTR)              // 73728
#define VSTR  272
#define VTSZ  (128 * VSTR)                  // 34816
#define VOFF_ (KOFF + 4 * 128 * ASTR)       // 147456
#define ASM_TOTAL (VOFF_ + 2 * VTSZ)        // 217088

__global__ __launch_bounds__(256, 1) void attn_tc(const float* __restrict__ hw) {
    extern __shared__ char smc[];
    const uint32_t sb = smem_u32(smc);
    const int t = threadIdx.x, w = t >> 5, lane = t & 31;
    const int b = blockIdx.z, h = blockIdx.y, bh = b * H_ + h;
    const int q0 = blockIdx.x * 128;

    // ---- Q tiles (once) ----
    {
        const __nv_bfloat16* qsrc[4] = { g_q1h, g_q1l, g_q2h, g_q2l };
        #pragma unroll
        for (int u = 0; u < 16; u++) {
            int idx = u * 256 + t;
            int tensor = idx >> 10, rem = idx & 1023;
            int row = rem >> 3, cc = rem & 7;
            const __nv_bfloat16* g = qsrc[tensor] + ((size_t)bh * R_ + q0 + row) * D_ + cc * 8;
            cp_async16(sb + QOFF + tensor * (128*ASTR) + row * ASTR + cc * 16, g);
        }
    }
    asm volatile("cp.async.commit_group;" ::: "memory");

    float Oc[2][16][4];
    #pragma unroll
    for (int tt = 0; tt < 2; tt++)
        #pragma unroll
        for (int nf = 0; nf < 16; nf++)
            #pragma unroll
            for (int q = 0; q < 4; q++) Oc[tt][nf][q] = 0.f;
    float mA[2] = { -1e30f, -1e30f }, mB[2] = { -1e30f, -1e30f };
    float sA[2] = { 0.f, 0.f },       sB[2] = { 0.f, 0.f };

    const uint32_t aq_base = sb + QOFF + (w*16 + (lane & 15)) * ASTR + ((lane >> 4) & 1) * 16;
    const uint32_t kb_base = sb + KOFF + ((lane & 7) + ((lane >> 4) & 1) * 8) * ASTR + ((lane >> 3) & 1) * 16;
    const uint32_t vb_base = sb + VOFF_ + ((lane & 7) + ((lane >> 4) & 1) * 8) * VSTR + ((lane >> 3) & 1) * 16;

    #pragma unroll 1
    for (int kt = 0; kt < 4; kt++) {
        __syncthreads();   // previous compute done before overwrite
        {
            const __nv_bfloat16* ksrc[4] = { g_k1h, g_k1l, g_k2h, g_k2l };
            #pragma unroll
            for (int u = 0; u < 16; u++) {
                int idx = u * 256 + t;
                int tensor = idx >> 10, rem = idx & 1023;
                int row = rem >> 3, cc = rem & 7;
                const __nv_bfloat16* g = ksrc[tensor] + ((size_t)bh * R_ + kt * 128 + row) * D_ + cc * 8;
                cp_async16(sb + KOFF + tensor * (128*ASTR) + row * ASTR + cc * 16, g);
            }
            #pragma unroll
            for (int u = 0; u < 16; u++) {
                int idx = u * 256 + t;
                int half = idx >> 11, rem = idx & 2047;
                int row = rem >> 4, cc = rem & 15;
                const __nv_bfloat16* g = (half ? g_vtl : g_vth)
                                       + ((size_t)bh * 128 + row) * R_ + kt * 128 + cc * 8;
                cp_async16(sb + VOFF_ + half * VTSZ + row * VSTR + cc * 16, g);
            }
        }
        asm volatile("cp.async.commit_group;" ::: "memory");
        asm volatile("cp.async.wait_group 0;" ::: "memory");
        __syncthreads();

        #pragma unroll
        for (int tt = 0; tt < 2; tt++) {
            // ---- S = Qtt @ Ktt^T (split 3-MMA) ----
            float S[16][4];
            #pragma unroll
            for (int nf = 0; nf < 16; nf++)
                #pragma unroll
                for (int q = 0; q < 4; q++) S[nf][q] = 0.f;

            #pragma unroll
            for (int kk = 0; kk < 4; kk++) {
                uint32_t ah[4], al[4];
                ldm_x4(ah, aq_base + (tt*2+0) * (128*ASTR) + kk*32);
                ldm_x4(al, aq_base + (tt*2+1) * (128*ASTR) + kk*32);
                #pragma unroll
                for (int np = 0; np < 8; np++) {
                    uint32_t bh4[4], bl4[4];
                    uint32_t ka = kb_base + (tt*2) * (128*ASTR) + np * 16 * ASTR + kk*32;
                    ldm_x4(bh4, ka);
                    ldm_x4(bl4, ka + 128*ASTR);
                    mma_bf16(S[2*np],   ah, bh4);
                    mma_bf16(S[2*np],   ah, bl4);
                    mma_bf16(S[2*np],   al, bh4);
                    mma_bf16(S[2*np+1], ah, bh4+2);
                    mma_bf16(S[2*np+1], ah, bl4+2);
                    mma_bf16(S[2*np+1], al, bh4+2);
                }
            }

            // ---- online softmax update ----
            float mla = -1e30f, mlb = -1e30f;
            #pragma unroll
            for (int nf = 0; nf < 16; nf++) {
                mla = fmaxf(mla, fmaxf(S[nf][0], S[nf][1]));
                mlb = fmaxf(mlb, fmaxf(S[nf][2], S[nf][3]));
            }
            mla = fmaxf(mla, __shfl_xor_sync(0xffffffffu, mla, 1));
            mla = fmaxf(mla, __shfl_xor_sync(0xffffffffu, mla, 2));
            mlb = fmaxf(mlb, __shfl_xor_sync(0xffffffffu, mlb, 1));
            mlb = fmaxf(mlb, __shfl_xor_sync(0xffffffffu, mlb, 2));
            float mna = fmaxf(mA[tt], mla), mnb = fmaxf(mB[tt], mlb);
            float fa = __expf(mA[tt] - mna), fb = __expf(mB[tt] - mnb);
            mA[tt] = mna; mB[tt] = mnb;
            float ra = 0.f, rb = 0.f;
            #pragma unroll
            for (int nf = 0; nf < 16; nf++) {
                S[nf][0] = __expf(S[nf][0] - mna);
                S[nf][1] = __expf(S[nf][1] - mna);
                S[nf][2] = __expf(S[nf][2] - mnb);
                S[nf][3] = __expf(S[nf][3] - mnb);
                ra += S[nf][0] + S[nf][1];
                rb += S[nf][2] + S[nf][3];
                Oc[tt][nf][0] *= fa; Oc[tt][nf][1] *= fa;
                Oc[tt][nf][2] *= fb; Oc[tt][nf][3] *= fb;
            }
            sA[tt] = sA[tt] * fa + ra;
            sB[tt] = sB[tt] * fb + rb;

            // ---- O += P @ V (split 3-MMA, P frags built in-register) ----
            #pragma unroll
            for (int kf = 0; kf < 8; kf++) {
                uint32_t pah[4], pal[4];
                #pragma unroll
                for (int half = 0; half < 2; half++) {
                    const float* sv = S[2*kf + half];
                    __nv_bfloat16 e0 = __float2bfloat16(sv[0]);
                    __nv_bfloat16 e1 = __float2bfloat16(sv[1]);
                    __nv_bfloat16 e2 = __float2bfloat16(sv[2]);
                    __nv_bfloat16 e3 = __float2bfloat16(sv[3]);
                    pah[half*2]   = pack_bf16x2(__bfloat162float(e0), __bfloat162float(e1));
                    pah[half*2+1] = pack_bf16x2(__bfloat162float(e2), __bfloat162float(e3));
                    pal[half*2]   = pack_bf16x2(sv[0] - __bfloat162float(e0),
                                                sv[1] - __bfloat162float(e1));
                    pal[half*2+1] = pack_bf16x2(sv[2] - __bfloat162float(e2),
                                                sv[3] - __bfloat162float(e3));
                }
                #pragma unroll
                for (int np = 0; np < 8; np++) {
                    uint32_t vh4[4], vl4[4];
                    uint32_t va = vb_base + np * 16 * VSTR + kf*32;
                    ldm_x4(vh4, va);
                    ldm_x4(vl4, va + VTSZ);
                    mma_bf16(Oc[tt][2*np],   pah, vh4);
                    mma_bf16(Oc[tt][2*np],   pah, vl4);
                    mma_bf16(Oc[tt][2*np],   pal, vh4);
                    mma_bf16(Oc[tt][2*np+1], pah, vh4+2);
                    mma_bf16(Oc[tt][2*np+1], pah, vl4+2);
                    mma_bf16(Oc[tt][2*np+1], pal, vh4+2);
                }
            }
        }
    }

    // ---- epilogue: combine, fused head rmsnorm * 0.2, bf16 hi/lo split ----
    #pragma unroll
    for (int tt = 0; tt < 2; tt++) {
        sA[tt] += __shfl_xor_sync(0xffffffffu, sA[tt], 1);
        sA[tt] += __shfl_xor_sync(0xffffffffu, sA[tt], 2);
        sB[tt] += __shfl_xor_sync(0xffffffffu, sB[tt], 1);
        sB[tt] += __shfl_xor_sync(0xffffffffu, sB[tt], 2);
    }
    float lam = g_lam;
    float i1a = 1.f / sA[0], i1b = 1.f / sB[0];
    float i2a = lam / sA[1], i2b = lam / sB[1];

    float Dv[16][4];
    float ssa = 0.f, ssb = 0.f;
    #pragma unroll
    for (int nf = 0; nf < 16; nf++) {
        Dv[nf][0] = Oc[0][nf][0] * i1a - Oc[1][nf][0] * i2a;
        Dv[nf][1] = Oc[0][nf][1] * i1a - Oc[1][nf][1] * i2a;
        Dv[nf][2] = Oc[0][nf][2] * i1b - Oc[1][nf][2] * i2b;
        Dv[nf][3] = Oc[0][nf][3] * i1b - Oc[1][nf][3] * i2b;
        ssa += Dv[nf][0]*Dv[nf][0] + Dv[nf][1]*Dv[nf][1];
        ssb += Dv[nf][2]*Dv[nf][2] + Dv[nf][3]*Dv[nf][3];
    }
    ssa += __shfl_xor_sync(0xffffffffu, ssa, 1);
    ssa += __shfl_xor_sync(0xffffffffu, ssa, 2);
    ssb += __shfl_xor_sync(0xffffffffu, ssb, 1);
    ssb += __shfl_xor_sync(0xffffffffu, ssb, 2);
    float na = 0.2f / sqrtf(ssa * (1.0f / 128.0f) + EPS_);
    float nb = 0.2f / sqrtf(ssb * (1.0f / 128.0f) + EPS_);

    int rowa = b * R_ + q0 + w * 16 + (lane >> 2);
    int colb = h * 128 + 2 * (lane & 3);
    #pragma unroll
    for (int nf = 0; nf < 16; nf++) {
        int col = colb + 8 * nf;
        float2 wv = *(const float2*)&hw[col - h * 128];
        float d0 = Dv[nf][0] * na * wv.x, d1 = Dv[nf][1] * na * wv.y;
        float d2 = Dv[nf][2] * nb * wv.x, d3 = Dv[nf][3] * nb * wv.y;
        __nv_bfloat16 h0 = __float2bfloat16(d0), h1 = __float2bfloat16(d1);
        __nv_bfloat16 h2 = __float2bfloat16(d2), h3 = __float2bfloat16(d3);
        __nv_bfloat162 hp0; hp0.x = h0; hp0.y = h1;
        __nv_bfloat162 hp1; hp1.x = h2; hp1.y = h3;
        __nv_bfloat162 lp0, lp1;
        lp0.x = __float2bfloat16(d0 - __bfloat162float(h0));
        lp0.y = __float2bfloat16(d1 - __bfloat162float(h1));
        lp1.x = __float2bfloat16(d2 - __bfloat162float(h2));
        lp1.y = __float2bfloat16(d3 - __bfloat162float(h3));
        *(__nv_bfloat162*)&g_dh[(size_t)rowa * C_ + col]       = hp0;
        *(__nv_bfloat162*)&g_dl[(size_t)rowa * C_ + col]       = lp0;
        *(__nv_bfloat162*)&g_dh[(size_t)(rowa + 8) * C_ + col] = hp1;
        *(__nv_bfloat162*)&g_dl[(size_t)(rowa + 8) * C_ + col] = lp1;
    }
}

// ---------------- upsample 512 -> 4096 ----------------
__global__ void upsample_kernel(float* __restrict__ out, const float* __restrict__ low) {
    int idx = blockIdx.x * blockDim.x + threadIdx.x;     // < 4194304
    int c = (idx & 255) * 4;
    int t = idx >> 8;                                    // 0..16383
    int j = t & 4095, b = t >> 12;
    float coord = fminf(fmaxf(0.125f * (float)j - 0.4375f, 0.0f), 511.0f);
    int lo = (int)coord;
    int hi = min(lo + 1, 511);
    float wgt = coord - (float)lo;
    const float* lb = low + (size_t)b * R_ * C_;
    float4 a  = *(const float4*)&lb[(size_t)lo * C_ + c];
    float4 bb = *(const float4*)&lb[(size_t)hi * C_ + c];
    float4 o = { a.x*(1.f-wgt) + bb.x*wgt, a.y*(1.f-wgt) + bb.y*wgt,
                 a.z*(1.f-wgt) + bb.z*wgt, a.w*(1.f-wgt) + bb.w*wgt };
    *(float4*)&out[(size_t)(b * L_ + j) * C_ + c] = o;
}

// ---------------- launch ----------------
extern "C" void kernel_launch(void* const* d_in, const int* in_sizes, int n_in,
                              void* d_out, int out_size) {
    (void)in_sizes; (void)n_in; (void)out_size;
    const float* x   = (const float*)d_in[0];
    const float* W[4] = { (const float*)d_in[1], (const float*)d_in[2],
                          (const float*)d_in[3], (const float*)d_in[4] };  // Wq,Wk,Wv,Wo
    const float* qn  = (const float*)d_in[5];
    const float* kn  = (const float*)d_in[6];
    const float* hw  = (const float*)d_in[7];
    const float* lq1 = (const float*)d_in[8];
    const float* lk1 = (const float*)d_in[9];
    const float* lq2 = (const float*)d_in[10];
    const float* lk2 = (const float*)d_in[11];

    float* out     = (float*)d_out;
    float* out_low = out + FULL_ELEMS;

    float *p_q, *p_k, *p_v;
    cudaGetSymbolAddress((void**)&p_q, g_q);
    cudaGetSymbolAddress((void**)&p_k, g_k);
    cudaGetSymbolAddress((void**)&p_v, g_v);
    __nv_bfloat16 *p_xdh, *p_xdl, *p_dh, *p_dl, *p_wh, *p_wl;
    cudaGetSymbolAddress((void**)&p_xdh, g_xdh);
    cudaGetSymbolAddress((void**)&p_xdl, g_xdl);
    cudaGetSymbolAddress((void**)&p_dh,  g_dh);
    cudaGetSymbolAddress((void**)&p_dl,  g_dl);
    cudaGetSymbolAddress((void**)&p_wh,  g_wh);
    cudaGetSymbolAddress((void**)&p_wl,  g_wl);

    static int attr_done = 0;
    if (!attr_done) {
        cudaFuncSetAttribute(gemm_tc<false>, cudaFuncAttributeMaxDynamicSharedMemorySize, GSM_TOTAL);
        cudaFuncSetAttribute(gemm_tc<true>,  cudaFuncAttributeMaxDynamicSharedMemorySize, GSM_TOTAL);
        cudaFuncSetAttribute(attn_tc,        cudaFuncAttributeMaxDynamicSharedMemorySize, ASM_TOTAL);
        cudaFuncSetAttribute(vtrans_kernel,  cudaFuncAttributeMaxDynamicSharedMemorySize, VT_SM);
        attr_done = 1;
    }

    lam_kernel<<<1, 32>>>(lq1, lk1, lq2, lk2);
    downsample_kernel<<<2048, 256>>>(x);
    for (int i = 0; i < 4; i++)
        split_kernel<<<256, 256>>>(W[i], p_wh + (size_t)i * C_ * C_, p_wl + (size_t)i * C_ * C_);

    // fused QKV GEMM: grid.x = 3 weights * 8 n-tiles
    gemm_tc<false><<<dim3(24, 16), 256, GSM_TOTAL>>>(p_xdh, p_xdl, p_wh, p_wl, p_q, p_k, p_v);

    normrope_kernel<<<16384, 128>>>(qn, kn);
    vtrans_kernel<<<dim3(4, 8, 4), 256, VT_SM>>>();
    attn_tc<<<dim3(4, 8, 4), 256, ASM_TOTAL>>>(hw);

    // Wo GEMM + SiLU (which==0 -> out_low)
    gemm_tc<true><<<dim3(8, 16), 256, GSM_TOTAL>>>(p_dh, p_dl,
        p_wh + 3*(size_t)C_*C_, p_wl + 3*(size_t)C_*C_, out_low, out_low, out_low);

    upsample_kernel<<<16384, 256>>>(out, out_low);
}

// round 15
// speedup vs baseline: 1.6254x; 1.0023x over previous
#include <cuda_runtime.h>
#include <cuda_bf16.h>
#include <math.h>
#include <stdint.h>

// ---------------- problem constants ----------------
#define B_  4
#define L_  4096
#define C_  1024
#define H_  8
#define D_  64      // C / (2H)
#define R_  512     // int(L^0.75)
#define M_  (B_*R_) // 2048 GEMM rows
#define FULL_ELEMS (B_*L_*C_)   // 16777216
#define LAMBDA_INIT 0.8f
#define EPS_ 1e-6f

// ---------------- device scratch (no allocs allowed) ----------------
__device__ float g_q   [M_*C_];
__device__ float g_k   [M_*C_];
__device__ float g_v   [M_*C_];
__device__ float g_lam;

// bf16 hi/lo split operands for tensor-core GEMMs
__device__ __nv_bfloat16 g_xdh[M_*C_], g_xdl[M_*C_];       // downsampled x
__device__ __nv_bfloat16 g_dh [M_*C_], g_dl [M_*C_];       // head-normed diff
__device__ __nv_bfloat16 g_wh [4][C_*C_], g_wl[4][C_*C_];  // Wq,Wk,Wv,Wo

// bf16 hi/lo Q/K (normrope output, q pre-scaled by 0.125) [B*H][R][D]
__device__ __nv_bfloat16 g_q1h[B_*H_*R_*D_], g_q1l[B_*H_*R_*D_];
__device__ __nv_bfloat16 g_q2h[B_*H_*R_*D_], g_q2l[B_*H_*R_*D_];
__device__ __nv_bfloat16 g_k1h[B_*H_*R_*D_], g_k1l[B_*H_*R_*D_];
__device__ __nv_bfloat16 g_k2h[B_*H_*R_*D_], g_k2l[B_*H_*R_*D_];
// transposed V hi/lo: [B*H][dim 128][key 512]
__device__ __nv_bfloat16 g_vth[B_*H_*128*R_], g_vtl[B_*H_*128*R_];

// ---------------- warp helpers ----------------
__device__ __forceinline__ float warp_sum(float v) {
    #pragma unroll
    for (int o = 16; o > 0; o >>= 1) v += __shfl_xor_sync(0xffffffffu, v, o);
    return v;
}

// ---------------- PTX helpers (HMMA path: valid on compute_103 PTX target) ----
__device__ __forceinline__ uint32_t smem_u32(const void* p) {
    uint32_t a;
    asm("{ .reg .u64 t; cvta.to.shared.u64 t, %1; cvt.u32.u64 %0, t; }" : "=r"(a) : "l"(p));
    return a;
}
__device__ __forceinline__ void cp_async16(uint32_t dst, const void* src) {
    asm volatile("cp.async.cg.shared.global [%0], [%1], 16;" :: "r"(dst), "l"(src) : "memory");
}
__device__ __forceinline__ void ldm_x4(uint32_t* r, uint32_t addr) {
    asm volatile("ldmatrix.sync.aligned.m8n8.x4.shared.b16 {%0,%1,%2,%3}, [%4];"
                 : "=r"(r[0]), "=r"(r[1]), "=r"(r[2]), "=r"(r[3]) : "r"(addr));
}
__device__ __forceinline__ void mma_bf16(float* c, const uint32_t* a, const uint32_t* b) {
    asm volatile(
        "mma.sync.aligned.m16n8k16.row.col.f32.bf16.bf16.f32 "
        "{%0,%1,%2,%3}, {%4,%5,%6,%7}, {%8,%9}, {%0,%1,%2,%3};"
        : "+f"(c[0]), "+f"(c[1]), "+f"(c[2]), "+f"(c[3])
        : "r"(a[0]), "r"(a[1]), "r"(a[2]), "r"(a[3]), "r"(b[0]), "r"(b[1]));
}
// pack two floats into bf16x2: low half = lo, high half = hi
__device__ __forceinline__ uint32_t pack_bf16x2(float lo, float hi) {
    uint32_t r;
    asm("cvt.rn.bf16x2.f32 %0, %1, %2;" : "=r"(r) : "f"(hi), "f"(lo));
    return r;
}

// ---------------- fp32 -> (bf16 hi, bf16 lo) split ----------------
__device__ __forceinline__ void split4(float4 o, __nv_bfloat16* hi, __nv_bfloat16* lo, size_t base) {
    __nv_bfloat16 h0 = __float2bfloat16(o.x), h1 = __float2bfloat16(o.y);
    __nv_bfloat16 h2 = __float2bfloat16(o.z), h3 = __float2bfloat16(o.w);
    __nv_bfloat16 l0 = __float2bfloat16(o.x - __bfloat162float(h0));
    __nv_bfloat16 l1 = __float2bfloat16(o.y - __bfloat162float(h1));
    __nv_bfloat16 l2 = __float2bfloat16(o.z - __bfloat162float(h2));
    __nv_bfloat16 l3 = __float2bfloat16(o.w - __bfloat162float(h3));
    __nv_bfloat162 ha; ha.x = h0; ha.y = h1;
    __nv_bfloat162 hb; hb.x = h2; hb.y = h3;
    __nv_bfloat162 la; la.x = l0; la.y = l1;
    __nv_bfloat162 lb; lb.x = l2; lb.y = l3;
    *(__nv_bfloat162*)&hi[base]     = ha;
    *(__nv_bfloat162*)&hi[base + 2] = hb;
    *(__nv_bfloat162*)&lo[base]     = la;
    *(__nv_bfloat162*)&lo[base + 2] = lb;
}

__global__ void split_kernel(const float* __restrict__ x,
                             __nv_bfloat16* __restrict__ hi, __nv_bfloat16* __restrict__ lo) {
    size_t i0 = ((size_t)blockIdx.x * blockDim.x + threadIdx.x) * 16;
    #pragma unroll
    for (int u = 0; u < 4; u++) {
        float4 v = *(const float4*)&x[i0 + u * 4];
        split4(v, hi, lo, i0 + u * 4);
    }
}

// ---------------- lambda scalar ----------------
__global__ void lam_kernel(const float* __restrict__ lq1, const float* __restrict__ lk1,
                           const float* __restrict__ lq2, const float* __restrict__ lk2) {
    int l = threadIdx.x;
    float s1 = lq1[l]*lk1[l] + lq1[l+32]*lk1[l+32];
    float s2 = lq2[l]*lk2[l] + lq2[l+32]*lk2[l+32];
    s1 = warp_sum(s1);
    s2 = warp_sum(s2);
    if (l == 0) g_lam = expf(s1) - expf(s2) + LAMBDA_INIT;
}

// ---------------- downsample + split: xd = 0.5*(x[8i+3] + x[8i+4]) ----------------
__global__ void downsample_kernel(const float* __restrict__ x) {
    int idx = blockIdx.x * blockDim.x + threadIdx.x;         // < 2048*256
    int c  = (idx & 255) * 4;
    int m  = idx >> 8;                                       // 0..2047
    int b  = m >> 9, i = m & 511;
    size_t src = ((size_t)b * L_ + 8 * i + 3) * C_ + c;
    float4 a  = *(const float4*)&x[src];
    float4 bb = *(const float4*)&x[src + C_];
    float4 o = { 0.5f*(a.x+bb.x), 0.5f*(a.y+bb.y), 0.5f*(a.z+bb.z), 0.5f*(a.w+bb.w) };
    split4(o, g_xdh, g_xdl, (size_t)m * C_ + c);
}

// ---------------- HMMA split-bf16 GEMM ----------------
// C[m,n] = sum_k A[m,k]*B[n,k], fp32 accum, 3 MMAs: Ah*Bh + Ah*Bl + Al*Bh.
// Block tile 128x128, 8 warps (warp tile 32x64), K-chunk 64, double-buffered cp.async.
// grid.x = 8 * numWeights: blockIdx.x>>3 selects the weight / output.
#define BK_      64
#define TSTRIDE  144                   // bytes per SMEM row (128 data + 16 pad)
#define TSIZE    (128 * TSTRIDE)       // 18432 per tensor
#define GSTAGE   (4 * TSIZE)           // Ah, Al, Bh, Bl
#define GSM_TOTAL (2 * GSTAGE)         // 147456

template<bool SILU>
__global__ __launch_bounds__(256, 1) void gemm_tc(
    const __nv_bfloat16* __restrict__ Ah, const __nv_bfloat16* __restrict__ Al,
    const __nv_bfloat16* __restrict__ BhBase, const __nv_bfloat16* __restrict__ BlBase,
    float* o0, float* o1, float* o2)
{
    extern __shared__ char smc[];
    const uint32_t sb = smem_u32(smc);
    const int t = threadIdx.x, w = t >> 5, lane = t & 31;
    const int wm = w & 3, wn = w >> 2;
    const int which = blockIdx.x >> 3;
    const int m0 = blockIdx.y * 128, n0 = (blockIdx.x & 7) * 128;
    float* Cout = (which == 0) ? o0 : ((which == 1) ? o1 : o2);
    const __nv_bfloat16* Bh = BhBase + (size_t)which * C_ * C_;
    const __nv_bfloat16* Bl = BlBase + (size_t)which * C_ * C_;

    const __nv_bfloat16* srcs[4] = { Ah, Al, Bh, Bl };

    float acc[2][8][4];
    #pragma unroll
    for (int i = 0; i < 2; i++)
        #pragma unroll
        for (int j = 0; j < 8; j++)
            #pragma unroll
            for (int q = 0; q < 4; q++) acc[i][j][q] = 0.f;

    const int ld_rowA = wm*32 + (lane & 15);
    const int ld_kA   = ((lane >> 4) & 1) * 16;
    const int ld_rowB = wn*64 + (lane & 7) + ((lane >> 4) & 1) * 8;
    const int ld_kB   = ((lane >> 3) & 1) * 16;

    #define ISSUE_LOAD(cidx) do { \
        const int _s = (cidx) & 1; \
        const int _k0 = (cidx) * BK_; \
        const uint32_t _sbase = sb + _s * GSTAGE; \
        _Pragma("unroll") \
        for (int u = 0; u < 16; u++) { \
            int idx = u * 256 + t; \
            int tensor = idx >> 10; \
            int rem = idx & 1023; \
            int row = rem >> 3, cc = rem & 7; \
            int rbase = (tensor < 2) ? m0 : n0; \
            const __nv_bfloat16* g = srcs[tensor] + (size_t)(rbase + row) * C_ + _k0 + cc * 8; \
            cp_async16(_sbase + tensor * TSIZE + row * TSTRIDE + cc * 16, g); \
        } \
        asm volatile("cp.async.commit_group;" ::: "memory"); \
    } while (0)

    ISSUE_LOAD(0);

    for (int c = 0; c < 16; c++) {
        if (c + 1 < 16) {
            ISSUE_LOAD(c + 1);
            asm volatile("cp.async.wait_group 1;" ::: "memory");
        } else {
            asm volatile("cp.async.wait_group 0;" ::: "memory");
        }
        __syncthreads();

        const uint32_t sbase = sb + (c & 1) * GSTAGE;
        #pragma unroll
        for (int ks = 0; ks < 4; ks++) {
            uint32_t ah[2][4], al[2][4];
            #pragma unroll
            for (int mf = 0; mf < 2; mf++) {
                uint32_t addr = sbase + (ld_rowA + mf*16) * TSTRIDE + ks*32 + ld_kA;
                ldm_x4(ah[mf], addr);
                ldm_x4(al[mf], addr + TSIZE);
            }
            uint32_t bh[8][2], bl[8][2];
            #pragma unroll
            for (int np = 0; np < 4; np++) {
                uint32_t addr = sbase + 2*TSIZE + (ld_rowB + np*16) * TSTRIDE + ks*32 + ld_kB;
                uint32_t r[4];
                ldm_x4(r, addr);
                bh[np*2][0] = r[0]; bh[np*2][1] = r[1];
                bh[np*2+1][0] = r[2]; bh[np*2+1][1] = r[3];
                ldm_x4(r, addr + TSIZE);
                bl[np*2][0] = r[0]; bl[np*2][1] = r[1];
                bl[np*2+1][0] = r[2]; bl[np*2+1][1] = r[3];
            }
            #pragma unroll
            for (int mf = 0; mf < 2; mf++)
                #pragma unroll
                for (int nf = 0; nf < 8; nf++) {
                    mma_bf16(acc[mf][nf], ah[mf], bh[nf]);
                    mma_bf16(acc[mf][nf], ah[mf], bl[nf]);
                    mma_bf16(acc[mf][nf], al[mf], bh[nf]);
                }
        }
        __syncthreads();
    }

    #pragma unroll
    for (int mf = 0; mf < 2; mf++) {
        int row = m0 + wm*32 + mf*16 + (lane >> 2);
        #pragma unroll
        for (int nf = 0; nf < 8; nf++) {
            int col = n0 + wn*64 + nf*8 + (lane & 3)*2;
            float2 v0 = { acc[mf][nf][0], acc[mf][nf][1] };
            float2 v1 = { acc[mf][nf][2], acc[mf][nf][3] };
            if (SILU) {
                v0.x = v0.x / (1.f + expf(-v0.x));
                v0.y = v0.y / (1.f + expf(-v0.y));
                v1.x = v1.x / (1.f + expf(-v1.x));
                v1.y = v1.y / (1.f + expf(-v1.y));
            }
            *(float2*)&Cout[(size_t)row * C_ + col]       = v0;
            *(float2*)&Cout[(size_t)(row + 8) * C_ + col] = v1;
        }
    }
    #undef ISSUE_LOAD
}

// ---------------- rmsnorm(d=64) + RoPE (pos = head index!) -> bf16 hi/lo ----------
// q additionally pre-scaled by 0.125 (attention logit scale).
__global__ void normrope_kernel(const float* __restrict__ qn_w, const float* __restrict__ kn_w) {
    int gw   = blockIdx.x * (blockDim.x >> 5) + (threadIdx.x >> 5);   // 0..65535
    int lane = threadIdx.x & 31;
    int j  = gw & 1;
    int h  = (gw >> 1) & 7;
    int i  = (gw >> 4) & 511;
    int b  = (gw >> 13) & 3;
    int qk = (gw >> 15) & 1;

    const float* src = (qk ? g_k : g_q) + ((size_t)(b * R_ + i) * C_ + h * 128 + j * 64);
    const float* wv  = qk ? kn_w : qn_w;

    float x1 = src[lane], x2 = src[lane + 32];
    float ss = warp_sum(x1*x1 + x2*x2);
    float inv = 1.0f / sqrtf(ss * (1.0f / 64.0f) + EPS_);
    float n1 = x1 * inv * wv[lane];
    float n2 = x2 * inv * wv[lane + 32];

    float freq = expf(-(float)lane * (9.210340371976184f / 32.0f));
    float s, c;
    sincosf((float)h * freq, &s, &c);

    float v1 = n1 * c - n2 * s;
    float v2 = n1 * s + n2 * c;
    if (!qk) { v1 *= 0.125f; v2 *= 0.125f; }

    __nv_bfloat16* dh_ = qk ? (j ? g_k2h : g_k1h) : (j ? g_q2h : g_q1h);
    __nv_bfloat16* dl_ = qk ? (j ? g_k2l : g_k1l) : (j ? g_q2l : g_q1l);
    size_t base = (size_t)((b * H_ + h) * R_ + i) * D_;
    __nv_bfloat16 h1 = __float2bfloat16(v1), h2 = __float2bfloat16(v2);
    dh_[base + lane]      = h1;
    dh_[base + lane + 32] = h2;
    dl_[base + lane]      = __float2bfloat16(v1 - __bfloat162float(h1));
    dl_[base + lane + 32] = __float2bfloat16(v2 - __bfloat162float(h2));
}

// ---------------- V transpose + split: g_v[b,key,h*128+dim] -> Vt[bh][dim][key] ----
#define VT_SM (128 * 132 * 4)
__global__ void vtrans_kernel() {
    extern __shared__ float smv[];          // [128 keys][132]
    const int kt = blockIdx.x, h = blockIdx.y, b = blockIdx.z;
    const int bh = b * H_ + h;
    const int t = threadIdx.x;              // 256

    #pragma unroll
    for (int u = 0; u < 16; u++) {
        int idx = u * 256 + t;              // 0..4095 float4 chunks
        int key = idx >> 5, c4 = (idx & 31) * 4;
        float4 v = *(const float4*)&g_v[((size_t)(b * R_ + kt * 128 + key)) * C_ + h * 128 + c4];
        *(float4*)&smv[key * 132 + c4] = v;
    }
    __syncthreads();

    int dim = t >> 1, k0 = (t & 1) * 64;
    size_t ob = ((size_t)bh * 128 + dim) * R_ + kt * 128 + k0;
    #pragma unroll
    for (int i = 0; i < 64; i += 2) {
        float e0 = smv[(k0 + i) * 132 + dim];
        float e1 = smv[(k0 + i + 1) * 132 + dim];
        __nv_bfloat16 h0 = __float2bfloat16(e0), h1 = __float2bfloat16(e1);
        __nv_bfloat162 hp; hp.x = h0; hp.y = h1;
        __nv_bfloat162 lp;
        lp.x = __float2bfloat16(e0 - __bfloat162float(h0));
        lp.y = __float2bfloat16(e1 - __bfloat162float(h1));
        *(__nv_bfloat162*)&g_vth[ob + i] = hp;
        *(__nv_bfloat162*)&g_vtl[ob + i] = lp;
    }
}

// ---------------- tensor-core differential flash attention + fused headnorm -------
// grid (4, H, B), 256 threads (8 warps x 16 q-rows). Online softmax per tensor.
#define ASTR  144
#define QOFF  0
#define KOFF  (4 * 128 * ASTR)              // 73728
#define VSTR  272
#define VTSZ  (128 * VSTR)                  // 34816
#define VOFF_ (KOFF + 4 * 128 * ASTR)       // 147456
#define ASM_TOTAL (VOFF_ + 2 * VTSZ)        // 217088

__global__ __launch_bounds__(256, 1) void attn_tc(const float* __restrict__ hw) {
    extern __shared__ char smc[];
    const uint32_t sb = smem_u32(smc);
    const int t = threadIdx.x, w = t >> 5, lane = t & 31;
    const int b = blockIdx.z, h = blockIdx.y, bh = b * H_ + h;
    const int q0 = blockIdx.x * 128;

    // ---- Q tiles (once) ----
    {
        const __nv_bfloat16* qsrc[4] = { g_q1h, g_q1l, g_q2h, g_q2l };
        #pragma unroll
        for (int u = 0; u < 16; u++) {
            int idx = u * 256 + t;
            int tensor = idx >> 10, rem = idx & 1023;
            int row = rem >> 3, cc = rem & 7;
            const __nv_bfloat16* g = qsrc[tensor] + ((size_t)bh * R_ + q0 + row) * D_ + cc * 8;
            cp_async16(sb + QOFF + tensor * (128*ASTR) + row * ASTR + cc * 16, g);
        }
    }
    asm volatile("cp.async.commit_group;" ::: "memory");

    float Oc[2][16][4];
    #pragma unroll
    for (int tt = 0; tt < 2; tt++)
        #pragma unroll
        for (int nf = 0; nf < 16; nf++)
            #pragma unroll
            for (int q = 0; q < 4; q++) Oc[tt][nf][q] = 0.f;
    float mA[2] = { -1e30f, -1e30f }, mB[2] = { -1e30f, -1e30f };
    float sA[2] = { 0.f, 0.f },       sB[2] = { 0.f, 0.f };

    const uint32_t aq_base = sb + QOFF + (w*16 + (lane & 15)) * ASTR + ((lane >> 4) & 1) * 16;
    const uint32_t kb_base = sb + KOFF + ((lane & 7) + ((lane >> 4) & 1) * 8) * ASTR + ((lane >> 3) & 1) * 16;
    const uint32_t vb_base = sb + VOFF_ + ((lane & 7) + ((lane >> 4) & 1) * 8) * VSTR + ((lane >> 3) & 1) * 16;

    #pragma unroll 1
    for (int kt = 0; kt < 4; kt++) {
        __syncthreads();   // previous compute done before overwrite
        {
            const __nv_bfloat16* ksrc[4] = { g_k1h, g_k1l, g_k2h, g_k2l };
            #pragma unroll
            for (int u = 0; u < 16; u++) {
                int idx = u * 256 + t;
                int tensor = idx >> 10, rem = idx & 1023;
                int row = rem >> 3, cc = rem & 7;
                const __nv_bfloat16* g = ksrc[tensor] + ((size_t)bh * R_ + kt * 128 + row) * D_ + cc * 8;
                cp_async16(sb + KOFF + tensor * (128*ASTR) + row * ASTR + cc * 16, g);
            }
            #pragma unroll
            for (int u = 0; u < 16; u++) {
                int idx = u * 256 + t;
                int half = idx >> 11, rem = idx & 2047;
                int row = rem >> 4, cc = rem & 15;
                const __nv_bfloat16* g = (half ? g_vtl : g_vth)
                                       + ((size_t)bh * 128 + row) * R_ + kt * 128 + cc * 8;
                cp_async16(sb + VOFF_ + half * VTSZ + row * VSTR + cc * 16, g);
            }
        }
        asm volatile("cp.async.commit_group;" ::: "memory");
        asm volatile("cp.async.wait_group 0;" ::: "memory");
        __syncthreads();

        #pragma unroll
        for (int tt = 0; tt < 2; tt++) {
            // ---- S = Qtt @ Ktt^T (split 3-MMA) ----
            float S[16][4];
            #pragma unroll
            for (int nf = 0; nf < 16; nf++)
                #pragma unroll
                for (int q = 0; q < 4; q++) S[nf][q] = 0.f;

            #pragma unroll
            for (int kk = 0; kk < 4; kk++) {
                uint32_t ah[4], al[4];
                ldm_x4(ah, aq_base + (tt*2+0) * (128*ASTR) + kk*32);
                ldm_x4(al, aq_base + (tt*2+1) * (128*ASTR) + kk*32);
                #pragma unroll
                for (int np = 0; np < 8; np++) {
                    uint32_t bh4[4], bl4[4];
                    uint32_t ka = kb_base + (tt*2) * (128*ASTR) + np * 16 * ASTR + kk*32;
                    ldm_x4(bh4, ka);
                    ldm_x4(bl4, ka + 128*ASTR);
                    mma_bf16(S[2*np],   ah, bh4);
                    mma_bf16(S[2*np],   ah, bl4);
                    mma_bf16(S[2*np],   al, bh4);
                    mma_bf16(S[2*np+1], ah, bh4+2);
                    mma_bf16(S[2*np+1], ah, bl4+2);
                    mma_bf16(S[2*np+1], al, bh4+2);
                }
            }

            // ---- online softmax update ----
            float mla = -1e30f, mlb = -1e30f;
            #pragma unroll
            for (int nf = 0; nf < 16; nf++) {
                mla = fmaxf(mla, fmaxf(S[nf][0], S[nf][1]));
                mlb = fmaxf(mlb, fmaxf(S[nf][2], S[nf][3]));
            }
            mla = fmaxf(mla, __shfl_xor_sync(0xffffffffu, mla, 1));
            mla = fmaxf(mla, __shfl_xor_sync(0xffffffffu, mla, 2));
            mlb = fmaxf(mlb, __shfl_xor_sync(0xffffffffu, mlb, 1));
            mlb = fmaxf(mlb, __shfl_xor_sync(0xffffffffu, mlb, 2));
            float mna = fmaxf(mA[tt], mla), mnb = fmaxf(mB[tt], mlb);
            float fa = __expf(mA[tt] - mna), fb = __expf(mB[tt] - mnb);
            mA[tt] = mna; mB[tt] = mnb;
            float ra = 0.f, rb = 0.f;
            #pragma unroll
            for (int nf = 0; nf < 16; nf++) {
                S[nf][0] = __expf(S[nf][0] - mna);
                S[nf][1] = __expf(S[nf][1] - mna);
                S[nf][2] = __expf(S[nf][2] - mnb);
                S[nf][3] = __expf(S[nf][3] - mnb);
                ra += S[nf][0] + S[nf][1];
                rb += S[nf][2] + S[nf][3];
                Oc[tt][nf][0] *= fa; Oc[tt][nf][1] *= fa;
                Oc[tt][nf][2] *= fb; Oc[tt][nf][3] *= fb;
            }
            sA[tt] = sA[tt] * fa + ra;
            sB[tt] = sB[tt] * fb + rb;

            // ---- O += P @ V (split 3-MMA, P frags built in-register) ----
            #pragma unroll
            for (int kf = 0; kf < 8; kf++) {
                uint32_t pah[4], pal[4];
                #pragma unroll
                for (int half = 0; half < 2; half++) {
                    const float* sv = S[2*kf + half];
                    __nv_bfloat16 e0 = __float2bfloat16(sv[0]);
                    __nv_bfloat16 e1 = __float2bfloat16(sv[1]);
                    __nv_bfloat16 e2 = __float2bfloat16(sv[2]);
                    __nv_bfloat16 e3 = __float2bfloat16(sv[3]);
                    pah[half*2]   = pack_bf16x2(__bfloat162float(e0), __bfloat162float(e1));
                    pah[half*2+1] = pack_bf16x2(__bfloat162float(e2), __bfloat162float(e3));
                    pal[half*2]   = pack_bf16x2(sv[0] - __bfloat162float(e0),
                                                sv[1] - __bfloat162float(e1));
                    pal[half*2+1] = pack_bf16x2(sv[2] - __bfloat162float(e2),
                                                sv[3] - __bfloat162float(e3));
                }
                #pragma unroll
                for (int np = 0; np < 8; np++) {
                    uint32_t vh4[4], vl4[4];
                    uint32_t va = vb_base + np * 16 * VSTR + kf*32;
                    ldm_x4(vh4, va);
                    ldm_x4(vl4, va + VTSZ);
                    mma_bf16(Oc[tt][2*np],   pah, vh4);
                    mma_bf16(Oc[tt][2*np],   pah, vl4);
                    mma_bf16(Oc[tt][2*np],   pal, vh4);
                    mma_bf16(Oc[tt][2*np+1], pah, vh4+2);
                    mma_bf16(Oc[tt][2*np+1], pah, vl4+2);
                    mma_bf16(Oc[tt][2*np+1], pal, vh4+2);
                }
            }
        }
    }

    // ---- epilogue: combine, fused head rmsnorm * 0.2, bf16 hi/lo split ----
    #pragma unroll
    for (int tt = 0; tt < 2; tt++) {
        sA[tt] += __shfl_xor_sync(0xffffffffu, sA[tt], 1);
        sA[tt] += __shfl_xor_sync(0xffffffffu, sA[tt], 2);
        sB[tt] += __shfl_xor_sync(0xffffffffu, sB[tt], 1);
        sB[tt] += __shfl_xor_sync(0xffffffffu, sB[tt], 2);
    }
    float lam = g_lam;
    float i1a = 1.f / sA[0], i1b = 1.f / sB[0];
    float i2a = lam / sA[1], i2b = lam / sB[1];

    float Dv[16][4];
    float ssa = 0.f, ssb = 0.f;
    #pragma unroll
    for (int nf = 0; nf < 16; nf++) {
        Dv[nf][0] = Oc[0][nf][0] * i1a - Oc[1][nf][0] * i2a;
        Dv[nf][1] = Oc[0][nf][1] * i1a - Oc[1][nf][1] * i2a;
        Dv[nf][2] = Oc[0][nf][2] * i1b - Oc[1][nf][2] * i2b;
        Dv[nf][3] = Oc[0][nf][3] * i1b - Oc[1][nf][3] * i2b;
        ssa += Dv[nf][0]*Dv[nf][0] + Dv[nf][1]*Dv[nf][1];
        ssb += Dv[nf][2]*Dv[nf][2] + Dv[nf][3]*Dv[nf][3];
    }
    ssa += __shfl_xor_sync(0xffffffffu, ssa, 1);
    ssa += __shfl_xor_sync(0xffffffffu, ssa, 2);
    ssb += __shfl_xor_sync(0xffffffffu, ssb, 1);
    ssb += __shfl_xor_sync(0xffffffffu, ssb, 2);
    float na = 0.2f / sqrtf(ssa * (1.0f / 128.0f) + EPS_);
    float nb = 0.2f / sqrtf(ssb * (1.0f / 128.0f) + EPS_);

    int rowa = b * R_ + q0 + w * 16 + (lane >> 2);
    int colb = h * 128 + 2 * (lane & 3);
    #pragma unroll
    for (int nf = 0; nf < 16; nf++) {
        int col = colb + 8 * nf;
        float2 wv = *(const float2*)&hw[col - h * 128];
        float d0 = Dv[nf][0] * na * wv.x, d1 = Dv[nf][1] * na * wv.y;
        float d2 = Dv[nf][2] * nb * wv.x, d3 = Dv[nf][3] * nb * wv.y;
        __nv_bfloat16 h0 = __float2bfloat16(d0), h1 = __float2bfloat16(d1);
        __nv_bfloat16 h2 = __float2bfloat16(d2), h3 = __float2bfloat16(d3);
        __nv_bfloat162 hp0; hp0.x = h0; hp0.y = h1;
        __nv_bfloat162 hp1; hp1.x = h2; hp1.y = h3;
        __nv_bfloat162 lp0, lp1;
        lp0.x = __float2bfloat16(d0 - __bfloat162float(h0));
        lp0.y = __float2bfloat16(d1 - __bfloat162float(h1));
        lp1.x = __float2bfloat16(d2 - __bfloat162float(h2));
        lp1.y = __float2bfloat16(d3 - __bfloat162float(h3));
        *(__nv_bfloat162*)&g_dh[(size_t)rowa * C_ + col]       = hp0;
        *(__nv_bfloat162*)&g_dl[(size_t)rowa * C_ + col]       = lp0;
        *(__nv_bfloat162*)&g_dh[(size_t)(rowa + 8) * C_ + col] = hp1;
        *(__nv_bfloat162*)&g_dl[(size_t)(rowa + 8) * C_ + col] = lp1;
    }
}

// ---------------- upsample 512 -> 4096 ----------------
__global__ void upsample_kernel(float* __restrict__ out, const float* __restrict__ low) {
    int idx = blockIdx.x * blockDim.x + threadIdx.x;     // < 4194304
    int c = (idx & 255) * 4;
    int t = idx >> 8;                                    // 0..16383
    int j = t & 4095, b = t >> 12;
    float coord = fminf(fmaxf(0.125f * (float)j - 0.4375f, 0.0f), 511.0f);
    int lo = (int)coord;
    int hi = min(lo + 1, 511);
    float wgt = coord - (float)lo;
    const float* lb = low + (size_t)b * R_ * C_;
    float4 a  = *(const float4*)&lb[(size_t)lo * C_ + c];
    float4 bb = *(const float4*)&lb[(size_t)hi * C_ + c];
    float4 o = { a.x*(1.f-wgt) + bb.x*wgt, a.y*(1.f-wgt) + bb.y*wgt,
                 a.z*(1.f-wgt) + bb.z*wgt, a.w*(1.f-wgt) + bb.w*wgt };
    *(float4*)&out[(size_t)(b * L_ + j) * C_ + c] = o;
}

// ---------------- launch ----------------
extern "C" void kernel_launch(void* const* d_in, const int* in_sizes, int n_in,
                              void* d_out, int out_size) {
    (void)in_sizes; (void)n_in; (void)out_size;
    const float* x   = (const float*)d_in[0];
    const float* W[4] = { (const float*)d_in[1], (const float*)d_in[2],
                          (const float*)d_in[3], (const float*)d_in[4] };  // Wq,Wk,Wv,Wo
    const float* qn  = (const float*)d_in[5];
    const float* kn  = (const float*)d_in[6];
    const float* hw  = (const float*)d_in[7];
    const float* lq1 = (const float*)d_in[8];
    const float* lk1 = (const float*)d_in[9];
    const float* lq2 = (const float*)d_in[10];
    const float* lk2 = (const float*)d_in[11];

    float* out     = (float*)d_out;
    float* out_low = out + FULL_ELEMS;

    float *p_q, *p_k, *p_v;
    cudaGetSymbolAddress((void**)&p_q, g_q);
    cudaGetSymbolAddress((void**)&p_k, g_k);
    cudaGetSymbolAddress((void**)&p_v, g_v);
    __nv_bfloat16 *p_xdh, *p_xdl, *p_dh, *p_dl, *p_wh, *p_wl;
    cudaGetSymbolAddress((void**)&p_xdh, g_xdh);
    cudaGetSymbolAddress((void**)&p_xdl, g_xdl);
    cudaGetSymbolAddress((void**)&p_dh,  g_dh);
    cudaGetSymbolAddress((void**)&p_dl,  g_dl);
    cudaGetSymbolAddress((void**)&p_wh,  g_wh);
    cudaGetSymbolAddress((void**)&p_wl,  g_wl);

    static int attr_done = 0;
    if (!attr_done) {
        cudaFuncSetAttribute(gemm_tc<false>, cudaFuncAttributeMaxDynamicSharedMemorySize, GSM_TOTAL);
        cudaFuncSetAttribute(gemm_tc<true>,  cudaFuncAttributeMaxDynamicSharedMemorySize, GSM_TOTAL);
        cudaFuncSetAttribute(attn_tc,        cudaFuncAttributeMaxDynamicSharedMemorySize, ASM_TOTAL);
        cudaFuncSetAttribute(vtrans_kernel,  cudaFuncAttributeMaxDynamicSharedMemorySize, VT_SM);
        attr_done = 1;
    }

    lam_kernel<<<1, 32>>>(lq1, lk1, lq2, lk2);
    downsample_kernel<<<2048, 256>>>(x);
    for (int i = 0; i < 4; i++)
        split_kernel<<<256, 256>>>(W[i], p_wh + (size_t)i * C_ * C_, p_wl + (size_t)i * C_ * C_);

    // fused QKV GEMM: grid.x = 3 weights * 8 n-tiles
    gemm_tc<false><<<dim3(24, 16), 256, GSM_TOTAL>>>(p_xdh, p_xdl, p_wh, p_wl, p_q, p_k, p_v);

    normrope_kernel<<<16384, 128>>>(qn, kn);
    vtrans_kernel<<<dim3(4, 8, 4), 256, VT_SM>>>();
    attn_tc<<<dim3(4, 8, 4), 256, ASM_TOTAL>>>(hw);

    // Wo GEMM + SiLU (which==0 -> out_low)
    gemm_tc<true><<<dim3(8, 16), 256, GSM_TOTAL>>>(p_dh, p_dl,
        p_wh + 3*(size_t)C_*C_, p_wl + 3*(size_t)C_*C_, out_low, out_low, out_low);

    upsample_kernel<<<16384, 256>>>(out, out_low);
}